// round 13
// baseline (speedup 1.0000x reference)
#include <cuda_runtime.h>
#include <cuda_bf16.h>
#include <math.h>
#include <stdint.h>

// Problem constants
#define BB 4
#define NN 2048
#define VD 256
#define CD 64
#define HH 4
#define DD 64
#define INNER 256
#define ROWS (BB * NN)   // 8192

typedef __nv_bfloat16 bf16;

// ---------------- scratch (device globals; no allocation allowed) ----------
__device__ float g_qkv[ROWS * 2 * INNER];
__device__ float g_qkc[ROWS * 2 * INNER];

__device__ bf16 g_Vnh[ROWS * VD];
__device__ bf16 g_Vnl[ROWS * VD];
__device__ bf16 g_Cnh[ROWS * CD];
__device__ bf16 g_Cnl[ROWS * CD];
__device__ bf16 g_ovph[ROWS * INNER];
__device__ bf16 g_ovpl[ROWS * INNER];
__device__ bf16 g_ocph[ROWS * INNER];
__device__ bf16 g_ocpl[ROWS * INNER];

__device__ bf16 g_Wvqk_h[VD * 512];
__device__ bf16 g_Wvqk_l[VD * 512];
__device__ bf16 g_Wcqk_h[CD * 512];
__device__ bf16 g_Wcqk_l[CD * 512];
__device__ bf16 g_Wvv_h[VD * INNER];
__device__ bf16 g_Wvv_l[VD * INNER];
__device__ bf16 g_Wcv_h[CD * INNER];
__device__ bf16 g_Wcv_l[CD * INNER];
__device__ bf16 g_Wov_h[INNER * VD];
__device__ bf16 g_Wov_l[INNER * VD];
__device__ bf16 g_Woc_h[INNER * CD];
__device__ bf16 g_Woc_l[INNER * CD];

__device__ bf16 g_Qh[ROWS * 512];
__device__ bf16 g_Ql[ROWS * 512];
__device__ bf16 g_Kh[ROWS * 512];
__device__ bf16 g_Kl[ROWS * 512];
__device__ bf16 g_Vh[ROWS * 512];
__device__ bf16 g_Vl[ROWS * 512];

// ---------------- helpers ---------------------------------------------------
static __device__ __forceinline__ uint32_t smem_u32(const void* p) {
    return (uint32_t)__cvta_generic_to_shared(p);
}

static __device__ __forceinline__ void split1(float v, bf16& h, bf16& l) {
    float vh = __bfloat162float(__float2bfloat16_rn(v));
    h = __float2bfloat16_rn(vh);
    l = __float2bfloat16_rn(v - vh);
}

static __device__ __forceinline__ void split_pack2(float a, float b,
                                                   uint32_t& hi, uint32_t& lo) {
    float ah = __bfloat162float(__float2bfloat16_rn(a));
    float bh2 = __bfloat162float(__float2bfloat16_rn(b));
    __nv_bfloat162 h2 = __floats2bfloat162_rn(ah, bh2);
    __nv_bfloat162 l2 = __floats2bfloat162_rn(a - ah, b - bh2);
    hi = *(uint32_t*)&h2;
    lo = *(uint32_t*)&l2;
}

#define LDSM_X4(r0,r1,r2,r3,addr) \
    asm volatile("ldmatrix.sync.aligned.m8n8.x4.shared.b16 {%0,%1,%2,%3}, [%4];" \
        : "=r"(r0),"=r"(r1),"=r"(r2),"=r"(r3) : "r"(addr))

#define LDSM_X4_T(r0,r1,r2,r3,addr) \
    asm volatile("ldmatrix.sync.aligned.m8n8.x4.trans.shared.b16 {%0,%1,%2,%3}, [%4];" \
        : "=r"(r0),"=r"(r1),"=r"(r2),"=r"(r3) : "r"(addr))

#define MMA_BF16(C, A, b0_, b1_) \
    asm volatile("mma.sync.aligned.m16n8k16.row.col.f32.bf16.bf16.f32 " \
        "{%0,%1,%2,%3}, {%4,%5,%6,%7}, {%8,%9}, {%0,%1,%2,%3};" \
        : "+f"((C)[0]), "+f"((C)[1]), "+f"((C)[2]), "+f"((C)[3]) \
        : "r"((A)[0]), "r"((A)[1]), "r"((A)[2]), "r"((A)[3]), "r"(b0_), "r"(b1_))

#define CP_A16(dst, src) \
    asm volatile("cp.async.cg.shared.global [%0], [%1], 16;" :: "r"(dst), "l"(src))
#define CP_COMMIT() asm volatile("cp.async.commit_group;")
#define CP_WAIT1() asm volatile("cp.async.wait_group 1;")
#define CP_WAIT0() asm volatile("cp.async.wait_group 0;")

// ---------------- LayerNorm + split-bf16 output ------------------------------
template <int DIM>
__global__ void ln_split_kernel(const float* __restrict__ x, const float* __restrict__ g,
                                const float* __restrict__ b,
                                bf16* __restrict__ oh, bf16* __restrict__ ol) {
    constexpr int NW = DIM / 32;
    __shared__ float red[NW];
    int row = blockIdx.x;
    int t = threadIdx.x;
    float v = x[(size_t)row * DIM + t];

    float s = v;
    #pragma unroll
    for (int o = 16; o; o >>= 1) s += __shfl_xor_sync(0xFFFFFFFFu, s, o);
    if ((t & 31) == 0) red[t >> 5] = s;
    __syncthreads();
    float tot = 0.f;
    #pragma unroll
    for (int i = 0; i < NW; i++) tot += red[i];
    float mean = tot / (float)DIM;
    __syncthreads();

    float d = v - mean;
    float s2 = d * d;
    #pragma unroll
    for (int o = 16; o; o >>= 1) s2 += __shfl_xor_sync(0xFFFFFFFFu, s2, o);
    if ((t & 31) == 0) red[t >> 5] = s2;
    __syncthreads();
    float var = 0.f;
    #pragma unroll
    for (int i = 0; i < NW; i++) var += red[i];
    var /= (float)DIM;

    float out = d * rsqrtf(var + 1e-5f) * g[t] + b[t];
    split1(out, oh[(size_t)row * DIM + t], ol[(size_t)row * DIM + t]);
}

// ---------------- merged weight split (one launch) ---------------------------
__global__ void splitw_all_kernel(const float* __restrict__ Wvqk, const float* __restrict__ Wcqk,
                                  const float* __restrict__ Wvv,  const float* __restrict__ Wcv,
                                  const float* __restrict__ Wov,  const float* __restrict__ Woc) {
    int i = blockIdx.x * 256 + threadIdx.x;
    if (i < 131072) { split1(Wvqk[i], g_Wvqk_h[i], g_Wvqk_l[i]); return; }
    i -= 131072;
    if (i < 32768)  { split1(Wcqk[i], g_Wcqk_h[i], g_Wcqk_l[i]); return; }
    i -= 32768;
    if (i < 65536)  { split1(Wvv[i],  g_Wvv_h[i],  g_Wvv_l[i]);  return; }
    i -= 65536;
    if (i < 16384)  { split1(Wcv[i],  g_Wcv_h[i],  g_Wcv_l[i]);  return; }
    i -= 16384;
    if (i < 65536)  { split1(Wov[i],  g_Wov_h[i],  g_Wov_l[i]);  return; }
    i -= 65536;
    if (i < 16384)  { split1(Woc[i],  g_Woc_h[i],  g_Woc_l[i]); }
}

// ---- RMSNorm over 512 + split-bf16 write to head-interleaved Q/K buffers ---
__global__ void rms512_split_kernel(const float* __restrict__ x, const float* __restrict__ s,
                                    bf16* __restrict__ Qh, bf16* __restrict__ Ql,
                                    bf16* __restrict__ Kh, bf16* __restrict__ Kl,
                                    int coff) {
    __shared__ float red[8];
    int row = blockIdx.x;
    int t = threadIdx.x;
    const float* xr = x + (size_t)row * 512;
    float a = xr[t], c = xr[t + 256];
    float ss = a * a + c * c;
    #pragma unroll
    for (int o = 16; o; o >>= 1) ss += __shfl_xor_sync(0xFFFFFFFFu, ss, o);
    if ((t & 31) == 0) red[t >> 5] = ss;
    __syncthreads();
    float tot = 0.f;
    #pragma unroll
    for (int i = 0; i < 8; i++) tot += red[i];
    float r = rsqrtf(tot / 512.f + 1e-6f);

    float qv = a * r * s[t] * 0.125f;
    float kv = c * r * s[t + 256];
    int h = t >> 6, d = t & 63;
    size_t di = (size_t)row * 512 + h * 128 + coff + d;
    split1(qv, Qh[di], Ql[di]);
    split1(kv, Kh[di], Kl[di]);
}

// ---------------- Tensor-core GEMM (split-bf16 x3, pipelined) ----------------
struct GemmSmem {
    bf16 Ah[2][128][72];
    bf16 Al[2][128][72];
    bf16 Bh[2][64][72];
    bf16 Bl[2][64][72];
};  // 110,592 B

__global__ void __launch_bounds__(256)
mma_gemm_kernel(const bf16* __restrict__ Ah_, const bf16* __restrict__ Al_,
                const bf16* __restrict__ Bh_, const bf16* __restrict__ Bl_,
                const float* __restrict__ bias, float* __restrict__ C,
                int K, int Nc,
                bf16* __restrict__ oh, bf16* __restrict__ ol, int coff) {
    extern __shared__ char smraw[];
    GemmSmem& sm = *(GemmSmem*)smraw;
    int tid = threadIdx.x;
    int lane = tid & 31;
    int wid = tid >> 5;
    int m0 = wid * 16;
    int g = lane >> 2, t4 = lane & 3;
    int bm0 = blockIdx.y * 128;
    int bn0 = blockIdx.x * 64;

    const uint32_t AHL = 2 * 128 * 72 * 2;
    const uint32_t BHL = 2 * 64 * 72 * 2;
    float cC[8][4] = {};

    {
        for (int idx = tid; idx < 1024; idx += 256) {
            int tok = idx >> 3;
            int c8 = (idx & 7) << 3;
            size_t abase = (size_t)(bm0 + tok) * K + c8;
            CP_A16(smem_u32(&sm.Ah[0][tok][c8]), &Ah_[abase]);
            CP_A16(smem_u32(&sm.Al[0][tok][c8]), &Al_[abase]);
        }
        for (int idx = tid; idx < 512; idx += 256) {
            int tok = idx >> 3;
            int c8 = (idx & 7) << 3;
            size_t bbase = (size_t)tok * Nc + bn0 + c8;
            CP_A16(smem_u32(&sm.Bh[0][tok][c8]), &Bh_[bbase]);
            CP_A16(smem_u32(&sm.Bl[0][tok][c8]), &Bl_[bbase]);
        }
        CP_COMMIT();
    }

    int NKS = K >> 6;
    for (int ks = 0; ks < NKS; ks++) {
        int st = ks & 1;
        if (ks + 1 < NKS) {
            int st1 = (ks + 1) & 1;
            int k1 = (ks + 1) * 64;
            for (int idx = tid; idx < 1024; idx += 256) {
                int tok = idx >> 3;
                int c8 = (idx & 7) << 3;
                size_t abase = (size_t)(bm0 + tok) * K + k1 + c8;
                CP_A16(smem_u32(&sm.Ah[st1][tok][c8]), &Ah_[abase]);
                CP_A16(smem_u32(&sm.Al[st1][tok][c8]), &Al_[abase]);
            }
            for (int idx = tid; idx < 512; idx += 256) {
                int tok = idx >> 3;
                int c8 = (idx & 7) << 3;
                size_t bbase = (size_t)(k1 + tok) * Nc + bn0 + c8;
                CP_A16(smem_u32(&sm.Bh[st1][tok][c8]), &Bh_[bbase]);
                CP_A16(smem_u32(&sm.Bl[st1][tok][c8]), &Bl_[bbase]);
            }
            CP_COMMIT();
            CP_WAIT1();
        } else {
            CP_WAIT0();
        }
        __syncthreads();

        #pragma unroll
        for (int j = 0; j < 4; j++) {
            uint32_t ah[4], al[4];
            uint32_t aaddr = smem_u32(&sm.Ah[st][m0 + (lane & 15)][j * 16 + (lane >> 4) * 8]);
            LDSM_X4(ah[0], ah[1], ah[2], ah[3], aaddr);
            LDSM_X4(al[0], al[1], al[2], al[3], aaddr + AHL);
            #pragma unroll
            for (int p = 0; p < 2; p++) {
                uint32_t bh2[2][4], bl2[2][4];
                #pragma unroll
                for (int q = 0; q < 2; q++) {
                    int nh = 2 * p + q;
                    uint32_t baddr = smem_u32(&sm.Bh[st][j * 16 + ((lane >> 3) & 1) * 8 + (lane & 7)]
                                                    [nh * 16 + (lane >> 4) * 8]);
                    LDSM_X4_T(bh2[q][0], bh2[q][1], bh2[q][2], bh2[q][3], baddr);
                    LDSM_X4_T(bl2[q][0], bl2[q][1], bl2[q][2], bl2[q][3], baddr + BHL);
                }
                float* c0 = cC[4 * p + 0]; float* c1 = cC[4 * p + 1];
                float* c2 = cC[4 * p + 2]; float* c3 = cC[4 * p + 3];
                MMA_BF16(c0, ah, bh2[0][0], bh2[0][1]);
                MMA_BF16(c1, ah, bh2[0][2], bh2[0][3]);
                MMA_BF16(c2, ah, bh2[1][0], bh2[1][1]);
                MMA_BF16(c3, ah, bh2[1][2], bh2[1][3]);
                MMA_BF16(c0, ah, bl2[0][0], bl2[0][1]);
                MMA_BF16(c1, ah, bl2[0][2], bl2[0][3]);
                MMA_BF16(c2, ah, bl2[1][0], bl2[1][1]);
                MMA_BF16(c3, ah, bl2[1][2], bl2[1][3]);
                MMA_BF16(c0, al, bh2[0][0], bh2[0][1]);
                MMA_BF16(c1, al, bh2[0][2], bh2[0][3]);
                MMA_BF16(c2, al, bh2[1][0], bh2[1][1]);
                MMA_BF16(c3, al, bh2[1][2], bh2[1][3]);
            }
        }
        __syncthreads();
    }

    int r0 = bm0 + m0 + g;
    if (oh) {
        #pragma unroll
        for (int nf = 0; nf < 8; nf++) {
            int n = bn0 + nf * 8 + t4 * 2;
            float b0 = bias[n], b1 = bias[n + 1];
            size_t di0 = (size_t)r0 * 512 + ((n >> 6) * 128 + coff + (n & 63));
            size_t di1 = (size_t)(r0 + 8) * 512 + ((n >> 6) * 128 + coff + (n & 63));
            uint32_t h0, l0, h1, l1;
            split_pack2(cC[nf][0] + b0, cC[nf][1] + b1, h0, l0);
            split_pack2(cC[nf][2] + b0, cC[nf][3] + b1, h1, l1);
            *(uint32_t*)&oh[di0] = h0; *(uint32_t*)&ol[di0] = l0;
            *(uint32_t*)&oh[di1] = h1; *(uint32_t*)&ol[di1] = l1;
        }
    } else {
        #pragma unroll
        for (int nf = 0; nf < 8; nf++) {
            int n = bn0 + nf * 8 + t4 * 2;
            float b0 = bias[n], b1 = bias[n + 1];
            *(float2*)&C[(size_t)r0 * Nc + n] =
                make_float2(cC[nf][0] + b0, cC[nf][1] + b1);
            *(float2*)&C[(size_t)(r0 + 8) * Nc + n] =
                make_float2(cC[nf][2] + b0, cC[nf][3] + b1);
        }
    }
}

// ---------------- Tensor-core attention (FA2, 128-token KV tiles) -----------
// TQ=128, 8 warps x 16 rows. Single-stage 128-token K and V buffers with
// phase-alternating cp.async prefetch (K and V consumed in different phases).
struct AttnSmem {
    bf16 Qh[128][136];
    bf16 Ql[128][136];
    bf16 Kh[128][136];
    bf16 Kl[128][136];
    bf16 Vh[128][136];
    bf16 Vl[128][136];
};  // 208,896 B -> 1 CTA/SM

__global__ void __launch_bounds__(256, 1)
attn_kernel(const bf16* __restrict__ gQh, const bf16* __restrict__ gQl,
            const bf16* __restrict__ gKh, const bf16* __restrict__ gKl,
            const bf16* __restrict__ gVh, const bf16* __restrict__ gVl,
            bf16* __restrict__ ovph, bf16* __restrict__ ovpl,
            bf16* __restrict__ ocph, bf16* __restrict__ ocpl) {
    extern __shared__ char smraw[];
    AttnSmem& sm = *(AttnSmem*)smraw;
    int tid = threadIdx.x;
    int lane = tid & 31;
    int wid = tid >> 5;
    int m0 = wid * 16;
    int g = lane >> 2, t4 = lane & 3;

    int bh_ = blockIdx.y;
    int b = bh_ >> 2;
    int h = bh_ & 3;
    int n0q = blockIdx.x * 128;

    const uint32_t HL = 128 * 136 * 2;   // hi -> lo offset, every buffer

    // ---- Fill Q tile ----
    for (int idx = tid; idx < 2048; idx += 256) {
        int tok = idx >> 4;
        int c8 = (idx & 15) << 3;
        size_t base = (size_t)(b * NN + n0q + tok) * 512 + h * 128 + c8;
        *(uint4*)&sm.Qh[tok][c8] = *(const uint4*)&gQh[base];
        *(uint4*)&sm.Ql[tok][c8] = *(const uint4*)&gQl[base];
    }

    float m_[2] = {-1e30f, -1e30f};
    float l_[2] = {0.f, 0.f};
    float cO[16][4] = {};

    // ---- prologue: prefetch K(0), then V(0) (separate groups) ----
    for (int idx = tid; idx < 2048; idx += 256) {
        int tok = idx >> 4;
        int c8 = (idx & 15) << 3;
        size_t base = (size_t)(b * NN + tok) * 512 + h * 128 + c8;
        CP_A16(smem_u32(&sm.Kh[tok][c8]), &gKh[base]);
        CP_A16(smem_u32(&sm.Kl[tok][c8]), &gKl[base]);
    }
    CP_COMMIT();
    for (int idx = tid; idx < 2048; idx += 256) {
        int tok = idx >> 4;
        int c8 = (idx & 15) << 3;
        size_t base = (size_t)(b * NN + tok) * 512 + h * 128 + c8;
        CP_A16(smem_u32(&sm.Vh[tok][c8]), &gVh[base]);
        CP_A16(smem_u32(&sm.Vl[tok][c8]), &gVl[base]);
    }
    CP_COMMIT();

    const int NT = NN / 128;   // 16 tiles of 128 tokens
    for (int jt = 0; jt < NT; jt++) {
        // wait K(jt) (V(jt) may still be in flight)
        CP_WAIT1();
        __syncthreads();

        // ---- S = Q @ K^T over 128 columns ----
        float cS[16][4] = {};
        #pragma unroll
        for (int kf = 0; kf < 8; kf++) {
            int k0 = kf * 16;
            uint32_t ah[4], al[4];
            uint32_t aaddr = smem_u32(&sm.Qh[m0 + (lane & 15)][k0 + (lane >> 4) * 8]);
            LDSM_X4(ah[0], ah[1], ah[2], ah[3], aaddr);
            LDSM_X4(al[0], al[1], al[2], al[3], aaddr + HL);
            #pragma unroll
            for (int p = 0; p < 4; p++) {          // nb pairs {0,1}..{6,7}
                uint32_t bh2[2][4], bl2[2][4];
                #pragma unroll
                for (int q = 0; q < 2; q++) {
                    int nb = 2 * p + q;
                    uint32_t baddr = smem_u32(&sm.Kh[nb * 16 + ((lane >> 4) & 1) * 8 + (lane & 7)]
                                                    [k0 + ((lane >> 3) & 1) * 8]);
                    LDSM_X4(bh2[q][0], bh2[q][1], bh2[q][2], bh2[q][3], baddr);
                    LDSM_X4(bl2[q][0], bl2[q][1], bl2[q][2], bl2[q][3], baddr + HL);
                }
                float* c0 = cS[4 * p + 0]; float* c1 = cS[4 * p + 1];
                float* c2 = cS[4 * p + 2]; float* c3 = cS[4 * p + 3];
                MMA_BF16(c0, ah, bh2[0][0], bh2[0][1]);
                MMA_BF16(c1, ah, bh2[0][2], bh2[0][3]);
                MMA_BF16(c2, ah, bh2[1][0], bh2[1][1]);
                MMA_BF16(c3, ah, bh2[1][2], bh2[1][3]);
                MMA_BF16(c0, ah, bl2[0][0], bl2[0][1]);
                MMA_BF16(c1, ah, bl2[0][2], bl2[0][3]);
                MMA_BF16(c2, ah, bl2[1][0], bl2[1][1]);
                MMA_BF16(c3, ah, bl2[1][2], bl2[1][3]);
                MMA_BF16(c0, al, bh2[0][0], bh2[0][1]);
                MMA_BF16(c1, al, bh2[0][2], bh2[0][3]);
                MMA_BF16(c2, al, bh2[1][0], bh2[1][1]);
                MMA_BF16(c3, al, bh2[1][2], bh2[1][3]);
            }
        }
        __syncthreads();   // K reads done -> safe to refill K

        // prefetch K(jt+1) while softmax + V-wait happen
        if (jt + 1 < NT) {
            int kn1 = (jt + 1) * 128;
            for (int idx = tid; idx < 2048; idx += 256) {
                int tok = idx >> 4;
                int c8 = (idx & 15) << 3;
                size_t base = (size_t)(b * NN + kn1 + tok) * 512 + h * 128 + c8;
                CP_A16(smem_u32(&sm.Kh[tok][c8]), &gKh[base]);
                CP_A16(smem_u32(&sm.Kl[tok][c8]), &gKl[base]);
            }
            CP_COMMIT();
        }

        // ---- Register softmax over 128 columns (once per 128 tokens) ----
        #pragma unroll
        for (int r = 0; r < 2; r++) {
            float mx = -1e30f;
            #pragma unroll
            for (int n = 0; n < 16; n++)
                mx = fmaxf(mx, fmaxf(cS[n][2 * r], cS[n][2 * r + 1]));
            mx = fmaxf(mx, __shfl_xor_sync(0xFFFFFFFFu, mx, 1));
            mx = fmaxf(mx, __shfl_xor_sync(0xFFFFFFFFu, mx, 2));
            float m_new = fmaxf(m_[r], mx);
            float alpha = __expf(m_[r] - m_new);
            float sum = 0.f;
            #pragma unroll
            for (int n = 0; n < 16; n++) {
                float p0 = __expf(cS[n][2 * r]     - m_new);
                float p1 = __expf(cS[n][2 * r + 1] - m_new);
                cS[n][2 * r] = p0; cS[n][2 * r + 1] = p1;
                sum += p0 + p1;
            }
            sum += __shfl_xor_sync(0xFFFFFFFFu, sum, 1);
            sum += __shfl_xor_sync(0xFFFFFFFFu, sum, 2);
            l_[r] = l_[r] * alpha + sum;
            m_[r] = m_new;
            #pragma unroll
            for (int nf = 0; nf < 16; nf++) {
                cO[nf][2 * r]     *= alpha;
                cO[nf][2 * r + 1] *= alpha;
            }
        }

        // wait V(jt) (K(jt+1) may still be in flight)
        if (jt + 1 < NT) { CP_WAIT1(); } else { CP_WAIT0(); }
        __syncthreads();

        // ---- O += P @ V over 128 tokens ----
        #pragma unroll
        for (int j = 0; j < 8; j++) {          // k-frags: tokens 16j..16j+15
            uint32_t PhA[4], PlA[4];
            split_pack2(cS[2 * j][0],     cS[2 * j][1],     PhA[0], PlA[0]);
            split_pack2(cS[2 * j][2],     cS[2 * j][3],     PhA[1], PlA[1]);
            split_pack2(cS[2 * j + 1][0], cS[2 * j + 1][1], PhA[2], PlA[2]);
            split_pack2(cS[2 * j + 1][2], cS[2 * j + 1][3], PhA[3], PlA[3]);
            #pragma unroll
            for (int p = 0; p < 4; p++) {      // nh pairs over V dims
                uint32_t bh2[2][4], bl2[2][4];
                #pragma unroll
                for (int q = 0; q < 2; q++) {
                    int nh = 2 * p + q;
                    uint32_t baddr = smem_u32(&sm.Vh[j * 16 + ((lane >> 3) & 1) * 8 + (lane & 7)]
                                                    [nh * 16 + (lane >> 4) * 8]);
                    LDSM_X4_T(bh2[q][0], bh2[q][1], bh2[q][2], bh2[q][3], baddr);
                    LDSM_X4_T(bl2[q][0], bl2[q][1], bl2[q][2], bl2[q][3], baddr + HL);
                }
                float* c0 = cO[4 * p + 0]; float* c1 = cO[4 * p + 1];
                float* c2 = cO[4 * p + 2]; float* c3 = cO[4 * p + 3];
                MMA_BF16(c0, PhA, bh2[0][0], bh2[0][1]);
                MMA_BF16(c1, PhA, bh2[0][2], bh2[0][3]);
                MMA_BF16(c2, PhA, bh2[1][0], bh2[1][1]);
                MMA_BF16(c3, PhA, bh2[1][2], bh2[1][3]);
                MMA_BF16(c0, PhA, bl2[0][0], bl2[0][1]);
                MMA_BF16(c1, PhA, bl2[0][2], bl2[0][3]);
                MMA_BF16(c2, PhA, bl2[1][0], bl2[1][1]);
                MMA_BF16(c3, PhA, bl2[1][2], bl2[1][3]);
                MMA_BF16(c0, PlA, bh2[0][0], bh2[0][1]);
                MMA_BF16(c1, PlA, bh2[0][2], bh2[0][3]);
                MMA_BF16(c2, PlA, bh2[1][0], bh2[1][1]);
                MMA_BF16(c3, PlA, bh2[1][2], bh2[1][3]);
            }
        }
        __syncthreads();   // V reads done -> safe to refill V

        // prefetch V(jt+1)
        if (jt + 1 < NT) {
            int kn1 = (jt + 1) * 128;
            for (int idx = tid; idx < 2048; idx += 256) {
                int tok = idx >> 4;
                int c8 = (idx & 15) << 3;
                size_t base = (size_t)(b * NN + kn1 + tok) * 512 + h * 128 + c8;
                CP_A16(smem_u32(&sm.Vh[tok][c8]), &gVh[base]);
                CP_A16(smem_u32(&sm.Vl[tok][c8]), &gVl[base]);
            }
            CP_COMMIT();
        }
    }

    // ---- Epilogue ----
    float li0 = 1.f / l_[0];
    float li1 = 1.f / l_[1];
    size_t row0 = (size_t)(b * NN + n0q + m0 + g);
    size_t row1 = row0 + 8;
    #pragma unroll
    for (int nf = 0; nf < 16; nf++) {
        int c = nf * 8 + t4 * 2;
        uint32_t h0, l0, h1, l1;
        split_pack2(cO[nf][0] * li0, cO[nf][1] * li0, h0, l0);
        split_pack2(cO[nf][2] * li1, cO[nf][3] * li1, h1, l1);
        if (c < 64) {
            size_t d0 = row0 * 256 + h * 64 + c, d1 = row1 * 256 + h * 64 + c;
            *(uint32_t*)&ovph[d0] = h0; *(uint32_t*)&ovpl[d0] = l0;
            *(uint32_t*)&ovph[d1] = h1; *(uint32_t*)&ovpl[d1] = l1;
        } else {
            size_t d0 = row0 * 256 + h * 64 + (c - 64), d1 = row1 * 256 + h * 64 + (c - 64);
            *(uint32_t*)&ocph[d0] = h0; *(uint32_t*)&ocpl[d0] = l0;
            *(uint32_t*)&ocph[d1] = h1; *(uint32_t*)&ocpl[d1] = l1;
        }
    }
}

// ---------------- launch ----------------------------------------------------
extern "C" void kernel_launch(void* const* d_in, const int* in_sizes, int n_in,
                              void* d_out, int out_size) {
    const float* V     = (const float*)d_in[0];
    const float* C     = (const float*)d_in[1];
    const float* vn_g  = (const float*)d_in[2];
    const float* vn_b  = (const float*)d_in[3];
    const float* cn_g  = (const float*)d_in[4];
    const float* cn_b  = (const float*)d_in[5];
    const float* W_vqk = (const float*)d_in[6];
    const float* b_vqk = (const float*)d_in[7];
    const float* rms_v = (const float*)d_in[8];
    const float* W_cqk = (const float*)d_in[9];
    const float* b_cqk = (const float*)d_in[10];
    const float* rms_c = (const float*)d_in[11];
    const float* W_vv  = (const float*)d_in[12];
    const float* b_vv  = (const float*)d_in[13];
    const float* W_cv  = (const float*)d_in[14];
    const float* b_cv  = (const float*)d_in[15];
    const float* W_ov  = (const float*)d_in[16];
    const float* b_ov  = (const float*)d_in[17];
    const float* W_oc  = (const float*)d_in[18];
    const float* b_oc  = (const float*)d_in[19];

    float* out_v = (float*)d_out;
    float* out_c = out_v + (size_t)ROWS * VD;

    float *pqkv, *pqkc;
    bf16 *pVnh, *pVnl, *pCnh, *pCnl;
    bf16 *pQh, *pQl, *pKh, *pKl, *pVh, *pVl;
    bf16 *povph, *povpl, *pocph, *pocpl;
    bf16 *wvqkh, *wvqkl, *wcqkh, *wcqkl, *wvvh, *wvvl, *wcvh, *wcvl, *wovh, *wovl, *woch, *wocl;
    cudaGetSymbolAddress((void**)&pqkv, g_qkv);
    cudaGetSymbolAddress((void**)&pqkc, g_qkc);
    cudaGetSymbolAddress((void**)&pVnh, g_Vnh);
    cudaGetSymbolAddress((void**)&pVnl, g_Vnl);
    cudaGetSymbolAddress((void**)&pCnh, g_Cnh);
    cudaGetSymbolAddress((void**)&pCnl, g_Cnl);
    cudaGetSymbolAddress((void**)&pQh, g_Qh);
    cudaGetSymbolAddress((void**)&pQl, g_Ql);
    cudaGetSymbolAddress((void**)&pKh, g_Kh);
    cudaGetSymbolAddress((void**)&pKl, g_Kl);
    cudaGetSymbolAddress((void**)&pVh, g_Vh);
    cudaGetSymbolAddress((void**)&pVl, g_Vl);
    cudaGetSymbolAddress((void**)&povph, g_ovph);
    cudaGetSymbolAddress((void**)&povpl, g_ovpl);
    cudaGetSymbolAddress((void**)&pocph, g_ocph);
    cudaGetSymbolAddress((void**)&pocpl, g_ocpl);
    cudaGetSymbolAddress((void**)&wvqkh, g_Wvqk_h);
    cudaGetSymbolAddress((void**)&wvqkl, g_Wvqk_l);
    cudaGetSymbolAddress((void**)&wcqkh, g_Wcqk_h);
    cudaGetSymbolAddress((void**)&wcqkl, g_Wcqk_l);
    cudaGetSymbolAddress((void**)&wvvh, g_Wvv_h);
    cudaGetSymbolAddress((void**)&wvvl, g_Wvv_l);
    cudaGetSymbolAddress((void**)&wcvh, g_Wcv_h);
    cudaGetSymbolAddress((void**)&wcvl, g_Wcv_l);
    cudaGetSymbolAddress((void**)&wovh, g_Wov_h);
    cudaGetSymbolAddress((void**)&wovl, g_Wov_l);
    cudaGetSymbolAddress((void**)&woch, g_Woc_h);
    cudaGetSymbolAddress((void**)&wocl, g_Woc_l);

    // 1. LayerNorms + merged weight split
    ln_split_kernel<VD><<<ROWS, VD>>>(V, vn_g, vn_b, pVnh, pVnl);
    ln_split_kernel<CD><<<ROWS, CD>>>(C, cn_g, cn_b, pCnh, pCnl);
    splitw_all_kernel<<<(327680 + 255) / 256, 256>>>(W_vqk, W_cqk, W_vv, W_cv, W_ov, W_oc);

    // 2. Projections
    cudaFuncSetAttribute(mma_gemm_kernel, cudaFuncAttributeMaxDynamicSharedMemorySize,
                         (int)sizeof(GemmSmem));
    int gsm = (int)sizeof(GemmSmem);
    mma_gemm_kernel<<<dim3(512 / 64, ROWS / 128), 256, gsm>>>(pVnh, pVnl, wvqkh, wvqkl, b_vqk, pqkv,
                                                              VD, 512, nullptr, nullptr, 0);
    mma_gemm_kernel<<<dim3(512 / 64, ROWS / 128), 256, gsm>>>(pCnh, pCnl, wcqkh, wcqkl, b_cqk, pqkc,
                                                              CD, 512, nullptr, nullptr, 0);
    mma_gemm_kernel<<<dim3(256 / 64, ROWS / 128), 256, gsm>>>(pVnh, pVnl, wvvh, wvvl, b_vv, nullptr,
                                                              VD, 256, pVh, pVl, 0);
    mma_gemm_kernel<<<dim3(256 / 64, ROWS / 128), 256, gsm>>>(pCnh, pCnl, wcvh, wcvl, b_cv, nullptr,
                                                              CD, 256, pVh, pVl, 64);

    // 3. RMS norms + split-bf16 Q/K writes
    rms512_split_kernel<<<ROWS, 256>>>(pqkv, rms_v, pQh, pQl, pKh, pKl, 0);
    rms512_split_kernel<<<ROWS, 256>>>(pqkc, rms_c, pQh, pQl, pKh, pKl, 64);

    // 4. Attention (128-token KV tiles, phase-alternating prefetch)
    cudaFuncSetAttribute(attn_kernel, cudaFuncAttributeMaxDynamicSharedMemorySize,
                         (int)sizeof(AttnSmem));
    attn_kernel<<<dim3(NN / 128, BB * HH), 256, sizeof(AttnSmem)>>>(pQh, pQl, pKh, pKl, pVh, pVl,
                                                                    povph, povpl, pocph, pocpl);

    // 5. Output projections
    mma_gemm_kernel<<<dim3(256 / 64, ROWS / 128), 256, gsm>>>(povph, povpl, wovh, wovl, b_ov, out_v,
                                                              INNER, VD, nullptr, nullptr, 0);
    mma_gemm_kernel<<<dim3(64 / 64, ROWS / 128), 256, gsm>>>(pocph, pocpl, woch, wocl, b_oc, out_c,
                                                             INNER, CD, nullptr, nullptr, 0);
}

// round 15
// speedup vs baseline: 1.0047x; 1.0047x over previous
#include <cuda_runtime.h>
#include <cuda_bf16.h>
#include <math.h>
#include <stdint.h>

// Problem constants
#define BB 4
#define NN 2048
#define VD 256
#define CD 64
#define HH 4
#define DD 64
#define INNER 256
#define ROWS (BB * NN)   // 8192

typedef __nv_bfloat16 bf16;

// ---------------- scratch (device globals; no allocation allowed) ----------
__device__ float g_qkv[ROWS * 2 * INNER];
__device__ float g_qkc[ROWS * 2 * INNER];

__device__ bf16 g_Vnh[ROWS * VD];
__device__ bf16 g_Vnl[ROWS * VD];
__device__ bf16 g_Cnh[ROWS * CD];
__device__ bf16 g_Cnl[ROWS * CD];
__device__ bf16 g_ovph[ROWS * INNER];
__device__ bf16 g_ovpl[ROWS * INNER];
__device__ bf16 g_ocph[ROWS * INNER];
__device__ bf16 g_ocpl[ROWS * INNER];

__device__ bf16 g_Wvqk_h[VD * 512];
__device__ bf16 g_Wvqk_l[VD * 512];
__device__ bf16 g_Wcqk_h[CD * 512];
__device__ bf16 g_Wcqk_l[CD * 512];
__device__ bf16 g_Wvv_h[VD * INNER];
__device__ bf16 g_Wvv_l[VD * INNER];
__device__ bf16 g_Wcv_h[CD * INNER];
__device__ bf16 g_Wcv_l[CD * INNER];
__device__ bf16 g_Wov_h[INNER * VD];
__device__ bf16 g_Wov_l[INNER * VD];
__device__ bf16 g_Woc_h[INNER * CD];
__device__ bf16 g_Woc_l[INNER * CD];

__device__ bf16 g_Qh[ROWS * 512];
__device__ bf16 g_Ql[ROWS * 512];
__device__ bf16 g_Kh[ROWS * 512];
__device__ bf16 g_Kl[ROWS * 512];
__device__ bf16 g_Vh[ROWS * 512];
__device__ bf16 g_Vl[ROWS * 512];

// ---------------- helpers ---------------------------------------------------
static __device__ __forceinline__ uint32_t smem_u32(const void* p) {
    return (uint32_t)__cvta_generic_to_shared(p);
}

static __device__ __forceinline__ void split1(float v, bf16& h, bf16& l) {
    float vh = __bfloat162float(__float2bfloat16_rn(v));
    h = __float2bfloat16_rn(vh);
    l = __float2bfloat16_rn(v - vh);
}

static __device__ __forceinline__ void split_pack2(float a, float b,
                                                   uint32_t& hi, uint32_t& lo) {
    float ah = __bfloat162float(__float2bfloat16_rn(a));
    float bh2 = __bfloat162float(__float2bfloat16_rn(b));
    __nv_bfloat162 h2 = __floats2bfloat162_rn(ah, bh2);
    __nv_bfloat162 l2 = __floats2bfloat162_rn(a - ah, b - bh2);
    hi = *(uint32_t*)&h2;
    lo = *(uint32_t*)&l2;
}

#define LDSM_X4(r0,r1,r2,r3,addr) \
    asm volatile("ldmatrix.sync.aligned.m8n8.x4.shared.b16 {%0,%1,%2,%3}, [%4];" \
        : "=r"(r0),"=r"(r1),"=r"(r2),"=r"(r3) : "r"(addr))

#define LDSM_X4_T(r0,r1,r2,r3,addr) \
    asm volatile("ldmatrix.sync.aligned.m8n8.x4.trans.shared.b16 {%0,%1,%2,%3}, [%4];" \
        : "=r"(r0),"=r"(r1),"=r"(r2),"=r"(r3) : "r"(addr))

#define MMA_BF16(C, A, b0_, b1_) \
    asm volatile("mma.sync.aligned.m16n8k16.row.col.f32.bf16.bf16.f32 " \
        "{%0,%1,%2,%3}, {%4,%5,%6,%7}, {%8,%9}, {%0,%1,%2,%3};" \
        : "+f"((C)[0]), "+f"((C)[1]), "+f"((C)[2]), "+f"((C)[3]) \
        : "r"((A)[0]), "r"((A)[1]), "r"((A)[2]), "r"((A)[3]), "r"(b0_), "r"(b1_))

#define CP_A16(dst, src) \
    asm volatile("cp.async.cg.shared.global [%0], [%1], 16;" :: "r"(dst), "l"(src))
#define CP_COMMIT() asm volatile("cp.async.commit_group;")
#define CP_WAIT1() asm volatile("cp.async.wait_group 1;")
#define CP_WAIT0() asm volatile("cp.async.wait_group 0;")

#define NBAR(id) asm volatile("bar.sync %0, %1;" :: "r"((int)(id)), "r"(128) : "memory")

// ---------------- LayerNorm + split-bf16 output ------------------------------
template <int DIM>
__global__ void ln_split_kernel(const float* __restrict__ x, const float* __restrict__ g,
                                const float* __restrict__ b,
                                bf16* __restrict__ oh, bf16* __restrict__ ol) {
    constexpr int NW = DIM / 32;
    __shared__ float red[NW];
    int row = blockIdx.x;
    int t = threadIdx.x;
    float v = x[(size_t)row * DIM + t];

    float s = v;
    #pragma unroll
    for (int o = 16; o; o >>= 1) s += __shfl_xor_sync(0xFFFFFFFFu, s, o);
    if ((t & 31) == 0) red[t >> 5] = s;
    __syncthreads();
    float tot = 0.f;
    #pragma unroll
    for (int i = 0; i < NW; i++) tot += red[i];
    float mean = tot / (float)DIM;
    __syncthreads();

    float d = v - mean;
    float s2 = d * d;
    #pragma unroll
    for (int o = 16; o; o >>= 1) s2 += __shfl_xor_sync(0xFFFFFFFFu, s2, o);
    if ((t & 31) == 0) red[t >> 5] = s2;
    __syncthreads();
    float var = 0.f;
    #pragma unroll
    for (int i = 0; i < NW; i++) var += red[i];
    var /= (float)DIM;

    float out = d * rsqrtf(var + 1e-5f) * g[t] + b[t];
    split1(out, oh[(size_t)row * DIM + t], ol[(size_t)row * DIM + t]);
}

// ---------------- merged weight split ----------------------------------------
__global__ void splitw_all_kernel(const float* __restrict__ Wvqk, const float* __restrict__ Wcqk,
                                  const float* __restrict__ Wvv,  const float* __restrict__ Wcv,
                                  const float* __restrict__ Wov,  const float* __restrict__ Woc) {
    int i = blockIdx.x * 256 + threadIdx.x;
    if (i < 131072) { split1(Wvqk[i], g_Wvqk_h[i], g_Wvqk_l[i]); return; }
    i -= 131072;
    if (i < 32768)  { split1(Wcqk[i], g_Wcqk_h[i], g_Wcqk_l[i]); return; }
    i -= 32768;
    if (i < 65536)  { split1(Wvv[i],  g_Wvv_h[i],  g_Wvv_l[i]);  return; }
    i -= 65536;
    if (i < 16384)  { split1(Wcv[i],  g_Wcv_h[i],  g_Wcv_l[i]);  return; }
    i -= 16384;
    if (i < 65536)  { split1(Wov[i],  g_Wov_h[i],  g_Wov_l[i]);  return; }
    i -= 65536;
    if (i < 16384)  { split1(Woc[i],  g_Woc_h[i],  g_Woc_l[i]); }
}

// ---- RMSNorm over 512 + split-bf16 write to head-interleaved Q/K buffers ---
__global__ void rms512_split_kernel(const float* __restrict__ x, const float* __restrict__ s,
                                    bf16* __restrict__ Qh, bf16* __restrict__ Ql,
                                    bf16* __restrict__ Kh, bf16* __restrict__ Kl,
                                    int coff) {
    __shared__ float red[8];
    int row = blockIdx.x;
    int t = threadIdx.x;
    const float* xr = x + (size_t)row * 512;
    float a = xr[t], c = xr[t + 256];
    float ss = a * a + c * c;
    #pragma unroll
    for (int o = 16; o; o >>= 1) ss += __shfl_xor_sync(0xFFFFFFFFu, ss, o);
    if ((t & 31) == 0) red[t >> 5] = ss;
    __syncthreads();
    float tot = 0.f;
    #pragma unroll
    for (int i = 0; i < 8; i++) tot += red[i];
    float r = rsqrtf(tot / 512.f + 1e-6f);

    float qv = a * r * s[t] * 0.125f;
    float kv = c * r * s[t + 256];
    int h = t >> 6, d = t & 63;
    size_t di = (size_t)row * 512 + h * 128 + coff + d;
    split1(qv, Qh[di], Ql[di]);
    split1(kv, Kh[di], Kl[di]);
}

// ---------------- Tensor-core GEMM (split-bf16 x3, pipelined) ----------------
struct GemmSmem {
    bf16 Ah[2][128][72];
    bf16 Al[2][128][72];
    bf16 Bh[2][64][72];
    bf16 Bl[2][64][72];
};  // 110,592 B

__global__ void __launch_bounds__(256)
mma_gemm_kernel(const bf16* __restrict__ Ah_, const bf16* __restrict__ Al_,
                const bf16* __restrict__ Bh_, const bf16* __restrict__ Bl_,
                const float* __restrict__ bias, float* __restrict__ C,
                int K, int Nc,
                bf16* __restrict__ oh, bf16* __restrict__ ol, int coff) {
    extern __shared__ char smraw[];
    GemmSmem& sm = *(GemmSmem*)smraw;
    int tid = threadIdx.x;
    int lane = tid & 31;
    int wid = tid >> 5;
    int m0 = wid * 16;
    int g = lane >> 2, t4 = lane & 3;
    int bm0 = blockIdx.y * 128;
    int bn0 = blockIdx.x * 64;

    const uint32_t AHL = 2 * 128 * 72 * 2;
    const uint32_t BHL = 2 * 64 * 72 * 2;
    float cC[8][4] = {};

    {
        for (int idx = tid; idx < 1024; idx += 256) {
            int tok = idx >> 3;
            int c8 = (idx & 7) << 3;
            size_t abase = (size_t)(bm0 + tok) * K + c8;
            CP_A16(smem_u32(&sm.Ah[0][tok][c8]), &Ah_[abase]);
            CP_A16(smem_u32(&sm.Al[0][tok][c8]), &Al_[abase]);
        }
        for (int idx = tid; idx < 512; idx += 256) {
            int tok = idx >> 3;
            int c8 = (idx & 7) << 3;
            size_t bbase = (size_t)tok * Nc + bn0 + c8;
            CP_A16(smem_u32(&sm.Bh[0][tok][c8]), &Bh_[bbase]);
            CP_A16(smem_u32(&sm.Bl[0][tok][c8]), &Bl_[bbase]);
        }
        CP_COMMIT();
    }

    int NKS = K >> 6;
    for (int ks = 0; ks < NKS; ks++) {
        int st = ks & 1;
        if (ks + 1 < NKS) {
            int st1 = (ks + 1) & 1;
            int k1 = (ks + 1) * 64;
            for (int idx = tid; idx < 1024; idx += 256) {
                int tok = idx >> 3;
                int c8 = (idx & 7) << 3;
                size_t abase = (size_t)(bm0 + tok) * K + k1 + c8;
                CP_A16(smem_u32(&sm.Ah[st1][tok][c8]), &Ah_[abase]);
                CP_A16(smem_u32(&sm.Al[st1][tok][c8]), &Al_[abase]);
            }
            for (int idx = tid; idx < 512; idx += 256) {
                int tok = idx >> 3;
                int c8 = (idx & 7) << 3;
                size_t bbase = (size_t)(k1 + tok) * Nc + bn0 + c8;
                CP_A16(smem_u32(&sm.Bh[st1][tok][c8]), &Bh_[bbase]);
                CP_A16(smem_u32(&sm.Bl[st1][tok][c8]), &Bl_[bbase]);
            }
            CP_COMMIT();
            CP_WAIT1();
        } else {
            CP_WAIT0();
        }
        __syncthreads();

        #pragma unroll
        for (int j = 0; j < 4; j++) {
            uint32_t ah[4], al[4];
            uint32_t aaddr = smem_u32(&sm.Ah[st][m0 + (lane & 15)][j * 16 + (lane >> 4) * 8]);
            LDSM_X4(ah[0], ah[1], ah[2], ah[3], aaddr);
            LDSM_X4(al[0], al[1], al[2], al[3], aaddr + AHL);
            #pragma unroll
            for (int p = 0; p < 2; p++) {
                uint32_t bh2[2][4], bl2[2][4];
                #pragma unroll
                for (int q = 0; q < 2; q++) {
                    int nh = 2 * p + q;
                    uint32_t baddr = smem_u32(&sm.Bh[st][j * 16 + ((lane >> 3) & 1) * 8 + (lane & 7)]
                                                    [nh * 16 + (lane >> 4) * 8]);
                    LDSM_X4_T(bh2[q][0], bh2[q][1], bh2[q][2], bh2[q][3], baddr);
                    LDSM_X4_T(bl2[q][0], bl2[q][1], bl2[q][2], bl2[q][3], baddr + BHL);
                }
                float* c0 = cC[4 * p + 0]; float* c1 = cC[4 * p + 1];
                float* c2 = cC[4 * p + 2]; float* c3 = cC[4 * p + 3];
                MMA_BF16(c0, ah, bh2[0][0], bh2[0][1]);
                MMA_BF16(c1, ah, bh2[0][2], bh2[0][3]);
                MMA_BF16(c2, ah, bh2[1][0], bh2[1][1]);
                MMA_BF16(c3, ah, bh2[1][2], bh2[1][3]);
                MMA_BF16(c0, ah, bl2[0][0], bl2[0][1]);
                MMA_BF16(c1, ah, bl2[0][2], bl2[0][3]);
                MMA_BF16(c2, ah, bl2[1][0], bl2[1][1]);
                MMA_BF16(c3, ah, bl2[1][2], bl2[1][3]);
                MMA_BF16(c0, al, bh2[0][0], bh2[0][1]);
                MMA_BF16(c1, al, bh2[0][2], bh2[0][3]);
                MMA_BF16(c2, al, bh2[1][0], bh2[1][1]);
                MMA_BF16(c3, al, bh2[1][2], bh2[1][3]);
            }
        }
        __syncthreads();
    }

    int r0 = bm0 + m0 + g;
    if (oh) {
        #pragma unroll
        for (int nf = 0; nf < 8; nf++) {
            int n = bn0 + nf * 8 + t4 * 2;
            float b0 = bias[n], b1 = bias[n + 1];
            size_t di0 = (size_t)r0 * 512 + ((n >> 6) * 128 + coff + (n & 63));
            size_t di1 = (size_t)(r0 + 8) * 512 + ((n >> 6) * 128 + coff + (n & 63));
            uint32_t h0, l0, h1, l1;
            split_pack2(cC[nf][0] + b0, cC[nf][1] + b1, h0, l0);
            split_pack2(cC[nf][2] + b0, cC[nf][3] + b1, h1, l1);
            *(uint32_t*)&oh[di0] = h0; *(uint32_t*)&ol[di0] = l0;
            *(uint32_t*)&oh[di1] = h1; *(uint32_t*)&ol[di1] = l1;
        }
    } else {
        #pragma unroll
        for (int nf = 0; nf < 8; nf++) {
            int n = bn0 + nf * 8 + t4 * 2;
            float b0 = bias[n], b1 = bias[n + 1];
            *(float2*)&C[(size_t)r0 * Nc + n] =
                make_float2(cC[nf][0] + b0, cC[nf][1] + b1);
            *(float2*)&C[(size_t)(r0 + 8) * Nc + n] =
                make_float2(cC[nf][2] + b0, cC[nf][3] + b1);
        }
    }
}

// ---------------- Tensor-core attention: two independent warp-groups --------
// 256 threads = 2 groups x 4 warps. Group g owns query rows [g*64, g*64+64),
// its own 64-token K/V buffers, named barrier (1+g), and starts the 32-tile
// KV loop 16 tiles out of phase. No cross-group sync -> softmax of one group
// overlaps MMAs of the other, keeping the tensor pipe fed.
struct AttnSmem {
    bf16 Qh[128][136];       // 34,816 B (hi); group rows disjoint
    bf16 Ql[128][136];
    bf16 Kh[2][64][136];     // [group][tok][dim]
    bf16 Kl[2][64][136];
    bf16 Vh[2][64][136];
    bf16 Vl[2][64][136];
};  // 208,896 B -> 1 CTA/SM

__global__ void __launch_bounds__(256, 1)
attn_kernel(const bf16* __restrict__ gQh, const bf16* __restrict__ gQl,
            const bf16* __restrict__ gKh, const bf16* __restrict__ gKl,
            const bf16* __restrict__ gVh, const bf16* __restrict__ gVl,
            bf16* __restrict__ ovph, bf16* __restrict__ ovpl,
            bf16* __restrict__ ocph, bf16* __restrict__ ocpl) {
    extern __shared__ char smraw[];
    AttnSmem& sm = *(AttnSmem*)smraw;
    int tid = threadIdx.x;
    int lane = tid & 31;
    int wid = tid >> 5;
    int grp = wid >> 2;            // 0 or 1
    int gtid = tid & 127;          // thread id within group
    int m0 = grp * 64 + (wid & 3) * 16;
    int g = lane >> 2, t4 = lane & 3;

    int bh_ = blockIdx.y;
    int b = bh_ >> 2;
    int h = bh_ & 3;
    int n0q = blockIdx.x * 128;

    const uint32_t HL = 64 * 136 * 2 * 2;   // Qh->Ql AND Kh[g]->Kl[g] / Vh[g]->Vl[g] (34,816 B)

    // ---- Group loads its own 64 Q rows ----
    for (int idx = gtid; idx < 1024; idx += 128) {
        int tok = grp * 64 + (idx >> 4);
        int c8 = (idx & 15) << 3;
        size_t base = (size_t)(b * NN + n0q + tok) * 512 + h * 128 + c8;
        *(uint4*)&sm.Qh[tok][c8] = *(const uint4*)&gQh[base];
        *(uint4*)&sm.Ql[tok][c8] = *(const uint4*)&gQl[base];
    }

    float m_[2] = {-1e30f, -1e30f};
    float l_[2] = {0.f, 0.f};
    float cO[16][4] = {};

    const int NT = NN / 64;        // 32 tiles
    int jt0 = grp * 16;            // phase offset between groups

    // ---- Group prologue: prefetch K(first), then V(first) ----
    {
        int kn0 = (jt0 & (NT - 1)) * 64;
        for (int idx = gtid; idx < 1024; idx += 128) {
            int tok = idx >> 4;
            int c8 = (idx & 15) << 3;
            size_t base = (size_t)(b * NN + kn0 + tok) * 512 + h * 128 + c8;
            CP_A16(smem_u32(&sm.Kh[grp][tok][c8]), &gKh[base]);
            CP_A16(smem_u32(&sm.Kl[grp][tok][c8]), &gKl[base]);
        }
        CP_COMMIT();
        for (int idx = gtid; idx < 1024; idx += 128) {
            int tok = idx >> 4;
            int c8 = (idx & 15) << 3;
            size_t base = (size_t)(b * NN + kn0 + tok) * 512 + h * 128 + c8;
            CP_A16(smem_u32(&sm.Vh[grp][tok][c8]), &gVh[base]);
            CP_A16(smem_u32(&sm.Vl[grp][tok][c8]), &gVl[base]);
        }
        CP_COMMIT();
    }

    for (int t = 0; t < NT; t++) {
        // wait K(cur); V(cur) may be in flight
        CP_WAIT1();
        NBAR(1 + grp);

        // ---- S = Q @ K^T (m16 x n64 per warp) ----
        float cS[8][4] = {};
        #pragma unroll
        for (int kf = 0; kf < 8; kf++) {
            int k0 = kf * 16;
            uint32_t ah[4], al[4];
            uint32_t aaddr = smem_u32(&sm.Qh[m0 + (lane & 15)][k0 + (lane >> 4) * 8]);
            LDSM_X4(ah[0], ah[1], ah[2], ah[3], aaddr);
            LDSM_X4(al[0], al[1], al[2], al[3], aaddr + HL);
            #pragma unroll
            for (int p = 0; p < 2; p++) {
                uint32_t bh2[2][4], bl2[2][4];
                #pragma unroll
                for (int q = 0; q < 2; q++) {
                    int nb = 2 * p + q;
                    uint32_t baddr = smem_u32(&sm.Kh[grp][nb * 16 + ((lane >> 4) & 1) * 8 + (lane & 7)]
                                                    [k0 + ((lane >> 3) & 1) * 8]);
                    LDSM_X4(bh2[q][0], bh2[q][1], bh2[q][2], bh2[q][3], baddr);
                    LDSM_X4(bl2[q][0], bl2[q][1], bl2[q][2], bl2[q][3], baddr + HL);
                }
                float* c0 = cS[4 * p + 0]; float* c1 = cS[4 * p + 1];
                float* c2 = cS[4 * p + 2]; float* c3 = cS[4 * p + 3];
                MMA_BF16(c0, ah, bh2[0][0], bh2[0][1]);
                MMA_BF16(c1, ah, bh2[0][2], bh2[0][3]);
                MMA_BF16(c2, ah, bh2[1][0], bh2[1][1]);
                MMA_BF16(c3, ah, bh2[1][2], bh2[1][3]);
                MMA_BF16(c0, ah, bl2[0][0], bl2[0][1]);
                MMA_BF16(c1, ah, bl2[0][2], bl2[0][3]);
                MMA_BF16(c2, ah, bl2[1][0], bl2[1][1]);
                MMA_BF16(c3, ah, bl2[1][2], bl2[1][3]);
                MMA_BF16(c0, al, bh2[0][0], bh2[0][1]);
                MMA_BF16(c1, al, bh2[0][2], bh2[0][3]);
                MMA_BF16(c2, al, bh2[1][0], bh2[1][1]);
                MMA_BF16(c3, al, bh2[1][2], bh2[1][3]);
            }
        }
        NBAR(1 + grp);   // K reads done -> safe to refill K

        // prefetch K(next)
        if (t + 1 < NT) {
            int kn1 = ((jt0 + t + 1) & (NT - 1)) * 64;
            for (int idx = gtid; idx < 1024; idx += 128) {
                int tok = idx >> 4;
                int c8 = (idx & 15) << 3;
                size_t base = (size_t)(b * NN + kn1 + tok) * 512 + h * 128 + c8;
                CP_A16(smem_u32(&sm.Kh[grp][tok][c8]), &gKh[base]);
                CP_A16(smem_u32(&sm.Kl[grp][tok][c8]), &gKl[base]);
            }
            CP_COMMIT();
        }

        // ---- Register online softmax (rows g, g+8) ----
        #pragma unroll
        for (int r = 0; r < 2; r++) {
            float mx = -1e30f;
            #pragma unroll
            for (int n = 0; n < 8; n++)
                mx = fmaxf(mx, fmaxf(cS[n][2 * r], cS[n][2 * r + 1]));
            mx = fmaxf(mx, __shfl_xor_sync(0xFFFFFFFFu, mx, 1));
            mx = fmaxf(mx, __shfl_xor_sync(0xFFFFFFFFu, mx, 2));
            float m_new = fmaxf(m_[r], mx);
            float alpha = __expf(m_[r] - m_new);
            float sum = 0.f;
            #pragma unroll
            for (int n = 0; n < 8; n++) {
                float p0 = __expf(cS[n][2 * r]     - m_new);
                float p1 = __expf(cS[n][2 * r + 1] - m_new);
                cS[n][2 * r] = p0; cS[n][2 * r + 1] = p1;
                sum += p0 + p1;
            }
            sum += __shfl_xor_sync(0xFFFFFFFFu, sum, 1);
            sum += __shfl_xor_sync(0xFFFFFFFFu, sum, 2);
            l_[r] = l_[r] * alpha + sum;
            m_[r] = m_new;
            #pragma unroll
            for (int nf = 0; nf < 16; nf++) {
                cO[nf][2 * r]     *= alpha;
                cO[nf][2 * r + 1] *= alpha;
            }
        }

        // wait V(cur); K(next) may be in flight
        if (t + 1 < NT) { CP_WAIT1(); } else { CP_WAIT0(); }
        NBAR(1 + grp);

        // ---- O += P @ V (4 k-frags x 8 nh) ----
        #pragma unroll
        for (int j = 0; j < 4; j++) {
            uint32_t PhA[4], PlA[4];
            split_pack2(cS[2 * j][0],     cS[2 * j][1],     PhA[0], PlA[0]);
            split_pack2(cS[2 * j][2],     cS[2 * j][3],     PhA[1], PlA[1]);
            split_pack2(cS[2 * j + 1][0], cS[2 * j + 1][1], PhA[2], PlA[2]);
            split_pack2(cS[2 * j + 1][2], cS[2 * j + 1][3], PhA[3], PlA[3]);
            #pragma unroll
            for (int p = 0; p < 4; p++) {
                uint32_t bh2[2][4], bl2[2][4];
                #pragma unroll
                for (int q = 0; q < 2; q++) {
                    int nh = 2 * p + q;
                    uint32_t baddr = smem_u32(&sm.Vh[grp][j * 16 + ((lane >> 3) & 1) * 8 + (lane & 7)]
                                                    [nh * 16 + (lane >> 4) * 8]);
                    LDSM_X4_T(bh2[q][0], bh2[q][1], bh2[q][2], bh2[q][3], baddr);
                    LDSM_X4_T(bl2[q][0], bl2[q][1], bl2[q][2], bl2[q][3], baddr + HL);
                }
                float* c0 = cO[4 * p + 0]; float* c1 = cO[4 * p + 1];
                float* c2 = cO[4 * p + 2]; float* c3 = cO[4 * p + 3];
                MMA_BF16(c0, PhA, bh2[0][0], bh2[0][1]);
                MMA_BF16(c1, PhA, bh2[0][2], bh2[0][3]);
                MMA_BF16(c2, PhA, bh2[1][0], bh2[1][1]);
                MMA_BF16(c3, PhA, bh2[1][2], bh2[1][3]);
                MMA_BF16(c0, PhA, bl2[0][0], bl2[0][1]);
                MMA_BF16(c1, PhA, bl2[0][2], bl2[0][3]);
                MMA_BF16(c2, PhA, bl2[1][0], bl2[1][1]);
                MMA_BF16(c3, PhA, bl2[1][2], bl2[1][3]);
                MMA_BF16(c0, PlA, bh2[0][0], bh2[0][1]);
                MMA_BF16(c1, PlA, bh2[0][2], bh2[0][3]);
                MMA_BF16(c2, PlA, bh2[1][0], bh2[1][1]);
                MMA_BF16(c3, PlA, bh2[1][2], bh2[1][3]);
            }
        }
        NBAR(1 + grp);   // V reads done -> safe to refill V

        // prefetch V(next)
        if (t + 1 < NT) {
            int kn1 = ((jt0 + t + 1) & (NT - 1)) * 64;
            for (int idx = gtid; idx < 1024; idx += 128) {
                int tok = idx >> 4;
                int c8 = (idx & 15) << 3;
                size_t base = (size_t)(b * NN + kn1 + tok) * 512 + h * 128 + c8;
                CP_A16(smem_u32(&sm.Vh[grp][tok][c8]), &gVh[base]);
                CP_A16(smem_u32(&sm.Vl[grp][tok][c8]), &gVl[base]);
            }
            CP_COMMIT();
        }
    }

    // ---- Epilogue: normalize, split-bf16 write ----
    float li0 = 1.f / l_[0];
    float li1 = 1.f / l_[1];
    size_t row0 = (size_t)(b * NN + n0q + m0 + g);
    size_t row1 = row0 + 8;
    #pragma unroll
    for (int nf = 0; nf < 16; nf++) {
        int c = nf * 8 + t4 * 2;
        uint32_t h0, l0, h1, l1;
        split_pack2(cO[nf][0] * li0, cO[nf][1] * li0, h0, l0);
        split_pack2(cO[nf][2] * li1, cO[nf][3] * li1, h1, l1);
        if (c < 64) {
            size_t d0 = row0 * 256 + h * 64 + c, d1 = row1 * 256 + h * 64 + c;
            *(uint32_t*)&ovph[d0] = h0; *(uint32_t*)&ovpl[d0] = l0;
            *(uint32_t*)&ovph[d1] = h1; *(uint32_t*)&ovpl[d1] = l1;
        } else {
            size_t d0 = row0 * 256 + h * 64 + (c - 64), d1 = row1 * 256 + h * 64 + (c - 64);
            *(uint32_t*)&ocph[d0] = h0; *(uint32_t*)&ocpl[d0] = l0;
            *(uint32_t*)&ocph[d1] = h1; *(uint32_t*)&ocpl[d1] = l1;
        }
    }
}

// ---------------- launch ----------------------------------------------------
extern "C" void kernel_launch(void* const* d_in, const int* in_sizes, int n_in,
                              void* d_out, int out_size) {
    const float* V     = (const float*)d_in[0];
    const float* C     = (const float*)d_in[1];
    const float* vn_g  = (const float*)d_in[2];
    const float* vn_b  = (const float*)d_in[3];
    const float* cn_g  = (const float*)d_in[4];
    const float* cn_b  = (const float*)d_in[5];
    const float* W_vqk = (const float*)d_in[6];
    const float* b_vqk = (const float*)d_in[7];
    const float* rms_v = (const float*)d_in[8];
    const float* W_cqk = (const float*)d_in[9];
    const float* b_cqk = (const float*)d_in[10];
    const float* rms_c = (const float*)d_in[11];
    const float* W_vv  = (const float*)d_in[12];
    const float* b_vv  = (const float*)d_in[13];
    const float* W_cv  = (const float*)d_in[14];
    const float* b_cv  = (const float*)d_in[15];
    const float* W_ov  = (const float*)d_in[16];
    const float* b_ov  = (const float*)d_in[17];
    const float* W_oc  = (const float*)d_in[18];
    const float* b_oc  = (const float*)d_in[19];

    float* out_v = (float*)d_out;
    float* out_c = out_v + (size_t)ROWS * VD;

    float *pqkv, *pqkc;
    bf16 *pVnh, *pVnl, *pCnh, *pCnl;
    bf16 *pQh, *pQl, *pKh, *pKl, *pVh, *pVl;
    bf16 *povph, *povpl, *pocph, *pocpl;
    bf16 *wvqkh, *wvqkl, *wcqkh, *wcqkl, *wvvh, *wvvl, *wcvh, *wcvl, *wovh, *wovl, *woch, *wocl;
    cudaGetSymbolAddress((void**)&pqkv, g_qkv);
    cudaGetSymbolAddress((void**)&pqkc, g_qkc);
    cudaGetSymbolAddress((void**)&pVnh, g_Vnh);
    cudaGetSymbolAddress((void**)&pVnl, g_Vnl);
    cudaGetSymbolAddress((void**)&pCnh, g_Cnh);
    cudaGetSymbolAddress((void**)&pCnl, g_Cnl);
    cudaGetSymbolAddress((void**)&pQh, g_Qh);
    cudaGetSymbolAddress((void**)&pQl, g_Ql);
    cudaGetSymbolAddress((void**)&pKh, g_Kh);
    cudaGetSymbolAddress((void**)&pKl, g_Kl);
    cudaGetSymbolAddress((void**)&pVh, g_Vh);
    cudaGetSymbolAddress((void**)&pVl, g_Vl);
    cudaGetSymbolAddress((void**)&povph, g_ovph);
    cudaGetSymbolAddress((void**)&povpl, g_ovpl);
    cudaGetSymbolAddress((void**)&pocph, g_ocph);
    cudaGetSymbolAddress((void**)&pocpl, g_ocpl);
    cudaGetSymbolAddress((void**)&wvqkh, g_Wvqk_h);
    cudaGetSymbolAddress((void**)&wvqkl, g_Wvqk_l);
    cudaGetSymbolAddress((void**)&wcqkh, g_Wcqk_h);
    cudaGetSymbolAddress((void**)&wcqkl, g_Wcqk_l);
    cudaGetSymbolAddress((void**)&wvvh, g_Wvv_h);
    cudaGetSymbolAddress((void**)&wvvl, g_Wvv_l);
    cudaGetSymbolAddress((void**)&wcvh, g_Wcv_h);
    cudaGetSymbolAddress((void**)&wcvl, g_Wcv_l);
    cudaGetSymbolAddress((void**)&wovh, g_Wov_h);
    cudaGetSymbolAddress((void**)&wovl, g_Wov_l);
    cudaGetSymbolAddress((void**)&woch, g_Woc_h);
    cudaGetSymbolAddress((void**)&wocl, g_Woc_l);

    // 1. LayerNorms + merged weight split
    ln_split_kernel<VD><<<ROWS, VD>>>(V, vn_g, vn_b, pVnh, pVnl);
    ln_split_kernel<CD><<<ROWS, CD>>>(C, cn_g, cn_b, pCnh, pCnl);
    splitw_all_kernel<<<(327680 + 255) / 256, 256>>>(W_vqk, W_cqk, W_vv, W_cv, W_ov, W_oc);

    // 2. Projections
    cudaFuncSetAttribute(mma_gemm_kernel, cudaFuncAttributeMaxDynamicSharedMemorySize,
                         (int)sizeof(GemmSmem));
    int gsm = (int)sizeof(GemmSmem);
    mma_gemm_kernel<<<dim3(512 / 64, ROWS / 128), 256, gsm>>>(pVnh, pVnl, wvqkh, wvqkl, b_vqk, pqkv,
                                                              VD, 512, nullptr, nullptr, 0);
    mma_gemm_kernel<<<dim3(512 / 64, ROWS / 128), 256, gsm>>>(pCnh, pCnl, wcqkh, wcqkl, b_cqk, pqkc,
                                                              CD, 512, nullptr, nullptr, 0);
    mma_gemm_kernel<<<dim3(256 / 64, ROWS / 128), 256, gsm>>>(pVnh, pVnl, wvvh, wvvl, b_vv, nullptr,
                                                              VD, 256, pVh, pVl, 0);
    mma_gemm_kernel<<<dim3(256 / 64, ROWS / 128), 256, gsm>>>(pCnh, pCnl, wcvh, wcvl, b_cv, nullptr,
                                                              CD, 256, pVh, pVl, 64);

    // 3. RMS norms + split-bf16 Q/K writes
    rms512_split_kernel<<<ROWS, 256>>>(pqkv, rms_v, pQh, pQl, pKh, pKl, 0);
    rms512_split_kernel<<<ROWS, 256>>>(pqkc, rms_c, pQh, pQl, pKh, pKl, 64);

    // 4. Attention (two independent warp-groups per CTA)
    cudaFuncSetAttribute(attn_kernel, cudaFuncAttributeMaxDynamicSharedMemorySize,
                         (int)sizeof(AttnSmem));
    attn_kernel<<<dim3(NN / 128, BB * HH), 256, sizeof(AttnSmem)>>>(pQh, pQl, pKh, pKl, pVh, pVl,
                                                                    povph, povpl, pocph, pocpl);

    // 5. Output projections
    mma_gemm_kernel<<<dim3(256 / 64, ROWS / 128), 256, gsm>>>(povph, povpl, wovh, wovl, b_ov, out_v,
                                                              INNER, VD, nullptr, nullptr, 0);
    mma_gemm_kernel<<<dim3(64 / 64, ROWS / 128), 256, gsm>>>(pocph, pocpl, woch, wocl, b_oc, out_c,
                                                             INNER, CD, nullptr, nullptr, 0);
}

// round 16
// speedup vs baseline: 1.2937x; 1.2876x over previous
#include <cuda_runtime.h>
#include <cuda_bf16.h>
#include <cuda_fp16.h>
#include <math.h>
#include <stdint.h>

// Problem constants
#define BB 4
#define NN 2048
#define VD 256
#define CD 64
#define HH 4
#define DD 64
#define INNER 256
#define ROWS (BB * NN)   // 8192

typedef __nv_bfloat16 bf16;

// ---------------- scratch (device globals; no allocation allowed) ----------
__device__ float g_qkv[ROWS * 2 * INNER];
__device__ float g_qkc[ROWS * 2 * INNER];

__device__ bf16 g_Vnh[ROWS * VD];
__device__ bf16 g_Vnl[ROWS * VD];
__device__ bf16 g_Cnh[ROWS * CD];
__device__ bf16 g_Cnl[ROWS * CD];
__device__ bf16 g_ovph[ROWS * INNER];
__device__ bf16 g_ovpl[ROWS * INNER];
__device__ bf16 g_ocph[ROWS * INNER];
__device__ bf16 g_ocpl[ROWS * INNER];

__device__ bf16 g_Wvqk_h[VD * 512];
__device__ bf16 g_Wvqk_l[VD * 512];
__device__ bf16 g_Wcqk_h[CD * 512];
__device__ bf16 g_Wcqk_l[CD * 512];
__device__ bf16 g_Wvv_h[VD * INNER];
__device__ bf16 g_Wvv_l[VD * INNER];
__device__ bf16 g_Wcv_h[CD * INNER];
__device__ bf16 g_Wcv_l[CD * INNER];
__device__ bf16 g_Wov_h[INNER * VD];
__device__ bf16 g_Wov_l[INNER * VD];
__device__ bf16 g_Woc_h[INNER * CD];
__device__ bf16 g_Woc_l[INNER * CD];

__device__ bf16 g_Qh[ROWS * 512];
__device__ bf16 g_Ql[ROWS * 512];
__device__ bf16 g_Kh[ROWS * 512];
__device__ bf16 g_Kl[ROWS * 512];
__device__ __half g_Vf[ROWS * 512];    // single fp16 V, head-interleaved

// ---------------- helpers ---------------------------------------------------
static __device__ __forceinline__ uint32_t smem_u32(const void* p) {
    return (uint32_t)__cvta_generic_to_shared(p);
}

static __device__ __forceinline__ void split1(float v, bf16& h, bf16& l) {
    float vh = __bfloat162float(__float2bfloat16_rn(v));
    h = __float2bfloat16_rn(vh);
    l = __float2bfloat16_rn(v - vh);
}

static __device__ __forceinline__ void split_pack2(float a, float b,
                                                   uint32_t& hi, uint32_t& lo) {
    float ah = __bfloat162float(__float2bfloat16_rn(a));
    float bh2 = __bfloat162float(__float2bfloat16_rn(b));
    __nv_bfloat162 h2 = __floats2bfloat162_rn(ah, bh2);
    __nv_bfloat162 l2 = __floats2bfloat162_rn(a - ah, b - bh2);
    hi = *(uint32_t*)&h2;
    lo = *(uint32_t*)&l2;
}

static __device__ __forceinline__ uint32_t pack_h2(float a, float b) {
    __half2 h = __floats2half2_rn(a, b);
    return *(uint32_t*)&h;
}

#define LDSM_X4(r0,r1,r2,r3,addr) \
    asm volatile("ldmatrix.sync.aligned.m8n8.x4.shared.b16 {%0,%1,%2,%3}, [%4];" \
        : "=r"(r0),"=r"(r1),"=r"(r2),"=r"(r3) : "r"(addr))

#define LDSM_X4_T(r0,r1,r2,r3,addr) \
    asm volatile("ldmatrix.sync.aligned.m8n8.x4.trans.shared.b16 {%0,%1,%2,%3}, [%4];" \
        : "=r"(r0),"=r"(r1),"=r"(r2),"=r"(r3) : "r"(addr))

#define MMA_BF16(C, A, b0_, b1_) \
    asm volatile("mma.sync.aligned.m16n8k16.row.col.f32.bf16.bf16.f32 " \
        "{%0,%1,%2,%3}, {%4,%5,%6,%7}, {%8,%9}, {%0,%1,%2,%3};" \
        : "+f"((C)[0]), "+f"((C)[1]), "+f"((C)[2]), "+f"((C)[3]) \
        : "r"((A)[0]), "r"((A)[1]), "r"((A)[2]), "r"((A)[3]), "r"(b0_), "r"(b1_))

#define MMA_F16(C, A, b0_, b1_) \
    asm volatile("mma.sync.aligned.m16n8k16.row.col.f32.f16.f16.f32 " \
        "{%0,%1,%2,%3}, {%4,%5,%6,%7}, {%8,%9}, {%0,%1,%2,%3};" \
        : "+f"((C)[0]), "+f"((C)[1]), "+f"((C)[2]), "+f"((C)[3]) \
        : "r"((A)[0]), "r"((A)[1]), "r"((A)[2]), "r"((A)[3]), "r"(b0_), "r"(b1_))

#define CP_A16(dst, src) \
    asm volatile("cp.async.cg.shared.global [%0], [%1], 16;" :: "r"(dst), "l"(src))
#define CP_COMMIT() asm volatile("cp.async.commit_group;")
#define CP_WAIT1() asm volatile("cp.async.wait_group 1;")
#define CP_WAIT0() asm volatile("cp.async.wait_group 0;")

// ---------------- LayerNorm + split-bf16 output ------------------------------
template <int DIM>
__global__ void ln_split_kernel(const float* __restrict__ x, const float* __restrict__ g,
                                const float* __restrict__ b,
                                bf16* __restrict__ oh, bf16* __restrict__ ol) {
    constexpr int NW = DIM / 32;
    __shared__ float red[NW];
    int row = blockIdx.x;
    int t = threadIdx.x;
    float v = x[(size_t)row * DIM + t];

    float s = v;
    #pragma unroll
    for (int o = 16; o; o >>= 1) s += __shfl_xor_sync(0xFFFFFFFFu, s, o);
    if ((t & 31) == 0) red[t >> 5] = s;
    __syncthreads();
    float tot = 0.f;
    #pragma unroll
    for (int i = 0; i < NW; i++) tot += red[i];
    float mean = tot / (float)DIM;
    __syncthreads();

    float d = v - mean;
    float s2 = d * d;
    #pragma unroll
    for (int o = 16; o; o >>= 1) s2 += __shfl_xor_sync(0xFFFFFFFFu, s2, o);
    if ((t & 31) == 0) red[t >> 5] = s2;
    __syncthreads();
    float var = 0.f;
    #pragma unroll
    for (int i = 0; i < NW; i++) var += red[i];
    var /= (float)DIM;

    float out = d * rsqrtf(var + 1e-5f) * g[t] + b[t];
    split1(out, oh[(size_t)row * DIM + t], ol[(size_t)row * DIM + t]);
}

// ---------------- merged weight split ----------------------------------------
__global__ void splitw_all_kernel(const float* __restrict__ Wvqk, const float* __restrict__ Wcqk,
                                  const float* __restrict__ Wvv,  const float* __restrict__ Wcv,
                                  const float* __restrict__ Wov,  const float* __restrict__ Woc) {
    int i = blockIdx.x * 256 + threadIdx.x;
    if (i < 131072) { split1(Wvqk[i], g_Wvqk_h[i], g_Wvqk_l[i]); return; }
    i -= 131072;
    if (i < 32768)  { split1(Wcqk[i], g_Wcqk_h[i], g_Wcqk_l[i]); return; }
    i -= 32768;
    if (i < 65536)  { split1(Wvv[i],  g_Wvv_h[i],  g_Wvv_l[i]);  return; }
    i -= 65536;
    if (i < 16384)  { split1(Wcv[i],  g_Wcv_h[i],  g_Wcv_l[i]);  return; }
    i -= 16384;
    if (i < 65536)  { split1(Wov[i],  g_Wov_h[i],  g_Wov_l[i]);  return; }
    i -= 65536;
    if (i < 16384)  { split1(Woc[i],  g_Woc_h[i],  g_Woc_l[i]); }
}

// ---- RMSNorm over 512 + split-bf16 write to head-interleaved Q/K buffers ---
__global__ void rms512_split_kernel(const float* __restrict__ x, const float* __restrict__ s,
                                    bf16* __restrict__ Qh, bf16* __restrict__ Ql,
                                    bf16* __restrict__ Kh, bf16* __restrict__ Kl,
                                    int coff) {
    __shared__ float red[8];
    int row = blockIdx.x;
    int t = threadIdx.x;
    const float* xr = x + (size_t)row * 512;
    float a = xr[t], c = xr[t + 256];
    float ss = a * a + c * c;
    #pragma unroll
    for (int o = 16; o; o >>= 1) ss += __shfl_xor_sync(0xFFFFFFFFu, ss, o);
    if ((t & 31) == 0) red[t >> 5] = ss;
    __syncthreads();
    float tot = 0.f;
    #pragma unroll
    for (int i = 0; i < 8; i++) tot += red[i];
    float r = rsqrtf(tot / 512.f + 1e-6f);

    float qv = a * r * s[t] * 0.125f;
    float kv = c * r * s[t + 256];
    int h = t >> 6, d = t & 63;
    size_t di = (size_t)row * 512 + h * 128 + coff + d;
    split1(qv, Qh[di], Ql[di]);
    split1(kv, Kh[di], Kl[di]);
}

// ---------------- Tensor-core GEMM (split-bf16 x3, pipelined) ----------------
struct GemmSmem {
    bf16 Ah[2][128][72];
    bf16 Al[2][128][72];
    bf16 Bh[2][64][72];
    bf16 Bl[2][64][72];
};  // 110,592 B

__global__ void __launch_bounds__(256)
mma_gemm_kernel(const bf16* __restrict__ Ah_, const bf16* __restrict__ Al_,
                const bf16* __restrict__ Bh_, const bf16* __restrict__ Bl_,
                const float* __restrict__ bias, float* __restrict__ C,
                int K, int Nc,
                bf16* __restrict__ oh, bf16* __restrict__ ol,
                __half* __restrict__ vf, int coff) {
    extern __shared__ char smraw[];
    GemmSmem& sm = *(GemmSmem*)smraw;
    int tid = threadIdx.x;
    int lane = tid & 31;
    int wid = tid >> 5;
    int m0 = wid * 16;
    int g = lane >> 2, t4 = lane & 3;
    int bm0 = blockIdx.y * 128;
    int bn0 = blockIdx.x * 64;

    const uint32_t AHL = 2 * 128 * 72 * 2;
    const uint32_t BHL = 2 * 64 * 72 * 2;
    float cC[8][4] = {};

    {
        for (int idx = tid; idx < 1024; idx += 256) {
            int tok = idx >> 3;
            int c8 = (idx & 7) << 3;
            size_t abase = (size_t)(bm0 + tok) * K + c8;
            CP_A16(smem_u32(&sm.Ah[0][tok][c8]), &Ah_[abase]);
            CP_A16(smem_u32(&sm.Al[0][tok][c8]), &Al_[abase]);
        }
        for (int idx = tid; idx < 512; idx += 256) {
            int tok = idx >> 3;
            int c8 = (idx & 7) << 3;
            size_t bbase = (size_t)tok * Nc + bn0 + c8;
            CP_A16(smem_u32(&sm.Bh[0][tok][c8]), &Bh_[bbase]);
            CP_A16(smem_u32(&sm.Bl[0][tok][c8]), &Bl_[bbase]);
        }
        CP_COMMIT();
    }

    int NKS = K >> 6;
    for (int ks = 0; ks < NKS; ks++) {
        int st = ks & 1;
        if (ks + 1 < NKS) {
            int st1 = (ks + 1) & 1;
            int k1 = (ks + 1) * 64;
            for (int idx = tid; idx < 1024; idx += 256) {
                int tok = idx >> 3;
                int c8 = (idx & 7) << 3;
                size_t abase = (size_t)(bm0 + tok) * K + k1 + c8;
                CP_A16(smem_u32(&sm.Ah[st1][tok][c8]), &Ah_[abase]);
                CP_A16(smem_u32(&sm.Al[st1][tok][c8]), &Al_[abase]);
            }
            for (int idx = tid; idx < 512; idx += 256) {
                int tok = idx >> 3;
                int c8 = (idx & 7) << 3;
                size_t bbase = (size_t)(k1 + tok) * Nc + bn0 + c8;
                CP_A16(smem_u32(&sm.Bh[st1][tok][c8]), &Bh_[bbase]);
                CP_A16(smem_u32(&sm.Bl[st1][tok][c8]), &Bl_[bbase]);
            }
            CP_COMMIT();
            CP_WAIT1();
        } else {
            CP_WAIT0();
        }
        __syncthreads();

        #pragma unroll
        for (int j = 0; j < 4; j++) {
            uint32_t ah[4], al[4];
            uint32_t aaddr = smem_u32(&sm.Ah[st][m0 + (lane & 15)][j * 16 + (lane >> 4) * 8]);
            LDSM_X4(ah[0], ah[1], ah[2], ah[3], aaddr);
            LDSM_X4(al[0], al[1], al[2], al[3], aaddr + AHL);
            #pragma unroll
            for (int p = 0; p < 2; p++) {
                uint32_t bh2[2][4], bl2[2][4];
                #pragma unroll
                for (int q = 0; q < 2; q++) {
                    int nh = 2 * p + q;
                    uint32_t baddr = smem_u32(&sm.Bh[st][j * 16 + ((lane >> 3) & 1) * 8 + (lane & 7)]
                                                    [nh * 16 + (lane >> 4) * 8]);
                    LDSM_X4_T(bh2[q][0], bh2[q][1], bh2[q][2], bh2[q][3], baddr);
                    LDSM_X4_T(bl2[q][0], bl2[q][1], bl2[q][2], bl2[q][3], baddr + BHL);
                }
                float* c0 = cC[4 * p + 0]; float* c1 = cC[4 * p + 1];
                float* c2 = cC[4 * p + 2]; float* c3 = cC[4 * p + 3];
                MMA_BF16(c0, ah, bh2[0][0], bh2[0][1]);
                MMA_BF16(c1, ah, bh2[0][2], bh2[0][3]);
                MMA_BF16(c2, ah, bh2[1][0], bh2[1][1]);
                MMA_BF16(c3, ah, bh2[1][2], bh2[1][3]);
                MMA_BF16(c0, ah, bl2[0][0], bl2[0][1]);
                MMA_BF16(c1, ah, bl2[0][2], bl2[0][3]);
                MMA_BF16(c2, ah, bl2[1][0], bl2[1][1]);
                MMA_BF16(c3, ah, bl2[1][2], bl2[1][3]);
                MMA_BF16(c0, al, bh2[0][0], bh2[0][1]);
                MMA_BF16(c1, al, bh2[0][2], bh2[0][3]);
                MMA_BF16(c2, al, bh2[1][0], bh2[1][1]);
                MMA_BF16(c3, al, bh2[1][2], bh2[1][3]);
            }
        }
        __syncthreads();
    }

    int r0 = bm0 + m0 + g;
    if (oh) {
        #pragma unroll
        for (int nf = 0; nf < 8; nf++) {
            int n = bn0 + nf * 8 + t4 * 2;
            float b0 = bias[n], b1 = bias[n + 1];
            size_t di0 = (size_t)r0 * 512 + ((n >> 6) * 128 + coff + (n & 63));
            size_t di1 = (size_t)(r0 + 8) * 512 + ((n >> 6) * 128 + coff + (n & 63));
            uint32_t h0, l0, h1, l1;
            split_pack2(cC[nf][0] + b0, cC[nf][1] + b1, h0, l0);
            split_pack2(cC[nf][2] + b0, cC[nf][3] + b1, h1, l1);
            *(uint32_t*)&oh[di0] = h0; *(uint32_t*)&ol[di0] = l0;
            *(uint32_t*)&oh[di1] = h1; *(uint32_t*)&ol[di1] = l1;
        }
    } else if (vf) {
        // fp16 single-value head-interleaved epilogue (V buffer)
        #pragma unroll
        for (int nf = 0; nf < 8; nf++) {
            int n = bn0 + nf * 8 + t4 * 2;
            float b0 = bias[n], b1 = bias[n + 1];
            size_t di0 = (size_t)r0 * 512 + ((n >> 6) * 128 + coff + (n & 63));
            size_t di1 = (size_t)(r0 + 8) * 512 + ((n >> 6) * 128 + coff + (n & 63));
            *(uint32_t*)&vf[di0] = pack_h2(cC[nf][0] + b0, cC[nf][1] + b1);
            *(uint32_t*)&vf[di1] = pack_h2(cC[nf][2] + b0, cC[nf][3] + b1);
        }
    } else {
        #pragma unroll
        for (int nf = 0; nf < 8; nf++) {
            int n = bn0 + nf * 8 + t4 * 2;
            float b0 = bias[n], b1 = bias[n + 1];
            *(float2*)&C[(size_t)r0 * Nc + n] =
                make_float2(cC[nf][0] + b0, cC[nf][1] + b1);
            *(float2*)&C[(size_t)(r0 + 8) * Nc + n] =
                make_float2(cC[nf][2] + b0, cC[nf][3] + b1);
        }
    }
}

// ---------------- Tensor-core attention (FA2 + cp.async pipeline) -----------
// TQ=128, 8 warps x 16 rows. 2-stage cp.async double buffer for K (split-bf16)
// and V (single fp16). QK = split-bf16 x3; PV = single fp16 MMA.
struct AttnSmem {
    bf16 Qh[128][136];        // 34,816 B
    bf16 Ql[128][136];
    bf16 Kh[2][64][136];      // 2 x 17,408 B
    bf16 Kl[2][64][136];
    __half Vf[2][64][136];    // 34,816 B total
};  // 174,080 B -> 1 CTA/SM

__global__ void __launch_bounds__(256, 1)
attn_kernel(const bf16* __restrict__ gQh, const bf16* __restrict__ gQl,
            const bf16* __restrict__ gKh, const bf16* __restrict__ gKl,
            const __half* __restrict__ gVf,
            bf16* __restrict__ ovph, bf16* __restrict__ ovpl,
            bf16* __restrict__ ocph, bf16* __restrict__ ocpl) {
    extern __shared__ char smraw[];
    AttnSmem& sm = *(AttnSmem*)smraw;
    int tid = threadIdx.x;
    int lane = tid & 31;
    int wid = tid >> 5;       // 0..7
    int m0 = wid * 16;
    int g = lane >> 2, t4 = lane & 3;

    int bh_ = blockIdx.y;
    int b = bh_ >> 2;
    int h = bh_ & 3;
    int n0q = blockIdx.x * 128;

    const uint32_t QHL = 128 * 136 * 2;      // Qh -> Ql
    const uint32_t KHL = 2 * 64 * 136 * 2;   // Kh[st] -> Kl[st]

    // ---- Fill Q tile (hi+lo) ----
    for (int idx = tid; idx < 2048; idx += 256) {
        int tok = idx >> 4;
        int c8 = (idx & 15) << 3;
        size_t base = (size_t)(b * NN + n0q + tok) * 512 + h * 128 + c8;
        *(uint4*)&sm.Qh[tok][c8] = *(const uint4*)&gQh[base];
        *(uint4*)&sm.Ql[tok][c8] = *(const uint4*)&gQl[base];
    }

    float m_[2] = {-1e30f, -1e30f};
    float l_[2] = {0.f, 0.f};
    float cO[16][4] = {};

    // ---- prologue: prefetch tile 0 into stage 0 ----
    {
        for (int idx = tid; idx < 1024; idx += 256) {
            int tok = idx >> 4;
            int c8 = (idx & 15) << 3;
            size_t base = (size_t)(b * NN + tok) * 512 + h * 128 + c8;
            CP_A16(smem_u32(&sm.Kh[0][tok][c8]), &gKh[base]);
            CP_A16(smem_u32(&sm.Kl[0][tok][c8]), &gKl[base]);
            CP_A16(smem_u32(&sm.Vf[0][tok][c8]), &gVf[base]);
        }
        CP_COMMIT();
    }

    const int NT = NN / 64;
    for (int jt = 0; jt < NT; jt++) {
        int st = jt & 1;
        if (jt + 1 < NT) {
            int kn1 = (jt + 1) * 64;
            int st1 = (jt + 1) & 1;
            for (int idx = tid; idx < 1024; idx += 256) {
                int tok = idx >> 4;
                int c8 = (idx & 15) << 3;
                size_t base = (size_t)(b * NN + kn1 + tok) * 512 + h * 128 + c8;
                CP_A16(smem_u32(&sm.Kh[st1][tok][c8]), &gKh[base]);
                CP_A16(smem_u32(&sm.Kl[st1][tok][c8]), &gKl[base]);
                CP_A16(smem_u32(&sm.Vf[st1][tok][c8]), &gVf[base]);
            }
            CP_COMMIT();
            CP_WAIT1();
        } else {
            CP_WAIT0();
        }
        __syncthreads();

        // ---- S = Q @ K^T : split-bf16 x3, term-major over nb pairs ----
        float cS[8][4] = {};
        #pragma unroll
        for (int kf = 0; kf < 8; kf++) {
            int k0 = kf * 16;
            uint32_t ah[4], al[4];
            uint32_t aaddr = smem_u32(&sm.Qh[m0 + (lane & 15)][k0 + (lane >> 4) * 8]);
            LDSM_X4(ah[0], ah[1], ah[2], ah[3], aaddr);
            LDSM_X4(al[0], al[1], al[2], al[3], aaddr + QHL);
            #pragma unroll
            for (int p = 0; p < 2; p++) {
                uint32_t bh2[2][4], bl2[2][4];
                #pragma unroll
                for (int q = 0; q < 2; q++) {
                    int nb = 2 * p + q;
                    uint32_t baddr = smem_u32(&sm.Kh[st][nb * 16 + ((lane >> 4) & 1) * 8 + (lane & 7)]
                                                    [k0 + ((lane >> 3) & 1) * 8]);
                    LDSM_X4(bh2[q][0], bh2[q][1], bh2[q][2], bh2[q][3], baddr);
                    LDSM_X4(bl2[q][0], bl2[q][1], bl2[q][2], bl2[q][3], baddr + KHL);
                }
                float* c0 = cS[4 * p + 0]; float* c1 = cS[4 * p + 1];
                float* c2 = cS[4 * p + 2]; float* c3 = cS[4 * p + 3];
                MMA_BF16(c0, ah, bh2[0][0], bh2[0][1]);
                MMA_BF16(c1, ah, bh2[0][2], bh2[0][3]);
                MMA_BF16(c2, ah, bh2[1][0], bh2[1][1]);
                MMA_BF16(c3, ah, bh2[1][2], bh2[1][3]);
                MMA_BF16(c0, ah, bl2[0][0], bl2[0][1]);
                MMA_BF16(c1, ah, bl2[0][2], bl2[0][3]);
                MMA_BF16(c2, ah, bl2[1][0], bl2[1][1]);
                MMA_BF16(c3, ah, bl2[1][2], bl2[1][3]);
                MMA_BF16(c0, al, bh2[0][0], bh2[0][1]);
                MMA_BF16(c1, al, bh2[0][2], bh2[0][3]);
                MMA_BF16(c2, al, bh2[1][0], bh2[1][1]);
                MMA_BF16(c3, al, bh2[1][2], bh2[1][3]);
            }
        }

        // ---- Register online softmax ----
        #pragma unroll
        for (int r = 0; r < 2; r++) {
            float mx = -1e30f;
            #pragma unroll
            for (int n = 0; n < 8; n++)
                mx = fmaxf(mx, fmaxf(cS[n][2 * r], cS[n][2 * r + 1]));
            mx = fmaxf(mx, __shfl_xor_sync(0xFFFFFFFFu, mx, 1));
            mx = fmaxf(mx, __shfl_xor_sync(0xFFFFFFFFu, mx, 2));
            float m_new = fmaxf(m_[r], mx);
            float alpha = __expf(m_[r] - m_new);
            float sum = 0.f;
            #pragma unroll
            for (int n = 0; n < 8; n++) {
                float p0 = __expf(cS[n][2 * r]     - m_new);
                float p1 = __expf(cS[n][2 * r + 1] - m_new);
                cS[n][2 * r] = p0; cS[n][2 * r + 1] = p1;
                sum += p0 + p1;
            }
            sum += __shfl_xor_sync(0xFFFFFFFFu, sum, 1);
            sum += __shfl_xor_sync(0xFFFFFFFFu, sum, 2);
            l_[r] = l_[r] * alpha + sum;
            m_[r] = m_new;
            #pragma unroll
            for (int nf = 0; nf < 16; nf++) {
                cO[nf][2 * r]     *= alpha;
                cO[nf][2 * r + 1] *= alpha;
            }
        }

        // ---- O += P @ V : single fp16 MMA per fragment ----
        #pragma unroll
        for (int j = 0; j < 4; j++) {
            uint32_t PhA[4];
            PhA[0] = pack_h2(cS[2 * j][0],     cS[2 * j][1]);
            PhA[1] = pack_h2(cS[2 * j][2],     cS[2 * j][3]);
            PhA[2] = pack_h2(cS[2 * j + 1][0], cS[2 * j + 1][1]);
            PhA[3] = pack_h2(cS[2 * j + 1][2], cS[2 * j + 1][3]);
            #pragma unroll
            for (int p = 0; p < 4; p++) {
                uint32_t bh2[2][4];
                #pragma unroll
                for (int q = 0; q < 2; q++) {
                    int nh = 2 * p + q;
                    uint32_t baddr = smem_u32(&sm.Vf[st][j * 16 + ((lane >> 3) & 1) * 8 + (lane & 7)]
                                                    [nh * 16 + (lane >> 4) * 8]);
                    LDSM_X4_T(bh2[q][0], bh2[q][1], bh2[q][2], bh2[q][3], baddr);
                }
                MMA_F16(cO[4 * p + 0], PhA, bh2[0][0], bh2[0][1]);
                MMA_F16(cO[4 * p + 1], PhA, bh2[0][2], bh2[0][3]);
                MMA_F16(cO[4 * p + 2], PhA, bh2[1][0], bh2[1][1]);
                MMA_F16(cO[4 * p + 3], PhA, bh2[1][2], bh2[1][3]);
            }
        }
        __syncthreads();   // stage st free for prefetch of jt+2
    }

    // ---- Epilogue: normalize, split-bf16 write ----
    float li0 = 1.f / l_[0];
    float li1 = 1.f / l_[1];
    size_t row0 = (size_t)(b * NN + n0q + m0 + g);
    size_t row1 = row0 + 8;
    #pragma unroll
    for (int nf = 0; nf < 16; nf++) {
        int c = nf * 8 + t4 * 2;
        uint32_t h0, l0, h1, l1;
        split_pack2(cO[nf][0] * li0, cO[nf][1] * li0, h0, l0);
        split_pack2(cO[nf][2] * li1, cO[nf][3] * li1, h1, l1);
        if (c < 64) {
            size_t d0 = row0 * 256 + h * 64 + c, d1 = row1 * 256 + h * 64 + c;
            *(uint32_t*)&ovph[d0] = h0; *(uint32_t*)&ovpl[d0] = l0;
            *(uint32_t*)&ovph[d1] = h1; *(uint32_t*)&ovpl[d1] = l1;
        } else {
            size_t d0 = row0 * 256 + h * 64 + (c - 64), d1 = row1 * 256 + h * 64 + (c - 64);
            *(uint32_t*)&ocph[d0] = h0; *(uint32_t*)&ocpl[d0] = l0;
            *(uint32_t*)&ocph[d1] = h1; *(uint32_t*)&ocpl[d1] = l1;
        }
    }
}

// ---------------- launch ----------------------------------------------------
extern "C" void kernel_launch(void* const* d_in, const int* in_sizes, int n_in,
                              void* d_out, int out_size) {
    const float* V     = (const float*)d_in[0];
    const float* C     = (const float*)d_in[1];
    const float* vn_g  = (const float*)d_in[2];
    const float* vn_b  = (const float*)d_in[3];
    const float* cn_g  = (const float*)d_in[4];
    const float* cn_b  = (const float*)d_in[5];
    const float* W_vqk = (const float*)d_in[6];
    const float* b_vqk = (const float*)d_in[7];
    const float* rms_v = (const float*)d_in[8];
    const float* W_cqk = (const float*)d_in[9];
    const float* b_cqk = (const float*)d_in[10];
    const float* rms_c = (const float*)d_in[11];
    const float* W_vv  = (const float*)d_in[12];
    const float* b_vv  = (const float*)d_in[13];
    const float* W_cv  = (const float*)d_in[14];
    const float* b_cv  = (const float*)d_in[15];
    const float* W_ov  = (const float*)d_in[16];
    const float* b_ov  = (const float*)d_in[17];
    const float* W_oc  = (const float*)d_in[18];
    const float* b_oc  = (const float*)d_in[19];

    float* out_v = (float*)d_out;
    float* out_c = out_v + (size_t)ROWS * VD;

    float *pqkv, *pqkc;
    bf16 *pVnh, *pVnl, *pCnh, *pCnl;
    bf16 *pQh, *pQl, *pKh, *pKl;
    __half* pVf;
    bf16 *povph, *povpl, *pocph, *pocpl;
    bf16 *wvqkh, *wvqkl, *wcqkh, *wcqkl, *wvvh, *wvvl, *wcvh, *wcvl, *wovh, *wovl, *woch, *wocl;
    cudaGetSymbolAddress((void**)&pqkv, g_qkv);
    cudaGetSymbolAddress((void**)&pqkc, g_qkc);
    cudaGetSymbolAddress((void**)&pVnh, g_Vnh);
    cudaGetSymbolAddress((void**)&pVnl, g_Vnl);
    cudaGetSymbolAddress((void**)&pCnh, g_Cnh);
    cudaGetSymbolAddress((void**)&pCnl, g_Cnl);
    cudaGetSymbolAddress((void**)&pQh, g_Qh);
    cudaGetSymbolAddress((void**)&pQl, g_Ql);
    cudaGetSymbolAddress((void**)&pKh, g_Kh);
    cudaGetSymbolAddress((void**)&pKl, g_Kl);
    cudaGetSymbolAddress((void**)&pVf, g_Vf);
    cudaGetSymbolAddress((void**)&povph, g_ovph);
    cudaGetSymbolAddress((void**)&povpl, g_ovpl);
    cudaGetSymbolAddress((void**)&pocph, g_ocph);
    cudaGetSymbolAddress((void**)&pocpl, g_ocpl);
    cudaGetSymbolAddress((void**)&wvqkh, g_Wvqk_h);
    cudaGetSymbolAddress((void**)&wvqkl, g_Wvqk_l);
    cudaGetSymbolAddress((void**)&wcqkh, g_Wcqk_h);
    cudaGetSymbolAddress((void**)&wcqkl, g_Wcqk_l);
    cudaGetSymbolAddress((void**)&wvvh, g_Wvv_h);
    cudaGetSymbolAddress((void**)&wvvl, g_Wvv_l);
    cudaGetSymbolAddress((void**)&wcvh, g_Wcv_h);
    cudaGetSymbolAddress((void**)&wcvl, g_Wcv_l);
    cudaGetSymbolAddress((void**)&wovh, g_Wov_h);
    cudaGetSymbolAddress((void**)&wovl, g_Wov_l);
    cudaGetSymbolAddress((void**)&woch, g_Woc_h);
    cudaGetSymbolAddress((void**)&wocl, g_Woc_l);

    // 1. LayerNorms + merged weight split
    ln_split_kernel<VD><<<ROWS, VD>>>(V, vn_g, vn_b, pVnh, pVnl);
    ln_split_kernel<CD><<<ROWS, CD>>>(C, cn_g, cn_b, pCnh, pCnl);
    splitw_all_kernel<<<(327680 + 255) / 256, 256>>>(W_vqk, W_cqk, W_vv, W_cv, W_ov, W_oc);

    // 2. Projections
    cudaFuncSetAttribute(mma_gemm_kernel, cudaFuncAttributeMaxDynamicSharedMemorySize,
                         (int)sizeof(GemmSmem));
    int gsm = (int)sizeof(GemmSmem);
    mma_gemm_kernel<<<dim3(512 / 64, ROWS / 128), 256, gsm>>>(pVnh, pVnl, wvqkh, wvqkl, b_vqk, pqkv,
                                                              VD, 512, nullptr, nullptr, nullptr, 0);
    mma_gemm_kernel<<<dim3(512 / 64, ROWS / 128), 256, gsm>>>(pCnh, pCnl, wcqkh, wcqkl, b_cqk, pqkc,
                                                              CD, 512, nullptr, nullptr, nullptr, 0);
    mma_gemm_kernel<<<dim3(256 / 64, ROWS / 128), 256, gsm>>>(pVnh, pVnl, wvvh, wvvl, b_vv, nullptr,
                                                              VD, 256, nullptr, nullptr, pVf, 0);
    mma_gemm_kernel<<<dim3(256 / 64, ROWS / 128), 256, gsm>>>(pCnh, pCnl, wcvh, wcvl, b_cv, nullptr,
                                                              CD, 256, nullptr, nullptr, pVf, 64);

    // 3. RMS norms + split-bf16 Q/K writes
    rms512_split_kernel<<<ROWS, 256>>>(pqkv, rms_v, pQh, pQl, pKh, pKl, 0);
    rms512_split_kernel<<<ROWS, 256>>>(pqkc, rms_c, pQh, pQl, pKh, pKl, 64);

    // 4. Attention (QK split-bf16 x3, PV single fp16)
    cudaFuncSetAttribute(attn_kernel, cudaFuncAttributeMaxDynamicSharedMemorySize,
                         (int)sizeof(AttnSmem));
    attn_kernel<<<dim3(NN / 128, BB * HH), 256, sizeof(AttnSmem)>>>(pQh, pQl, pKh, pKl, pVf,
                                                                    povph, povpl, pocph, pocpl);

    // 5. Output projections
    mma_gemm_kernel<<<dim3(256 / 64, ROWS / 128), 256, gsm>>>(povph, povpl, wovh, wovl, b_ov, out_v,
                                                              INNER, VD, nullptr, nullptr, nullptr, 0);
    mma_gemm_kernel<<<dim3(64 / 64, ROWS / 128), 256, gsm>>>(pocph, pocpl, woch, wocl, b_oc, out_c,
                                                             INNER, CD, nullptr, nullptr, nullptr, 0);
}

// round 17
// speedup vs baseline: 1.8152x; 1.4031x over previous
#include <cuda_runtime.h>
#include <cuda_bf16.h>
#include <cuda_fp16.h>
#include <math.h>
#include <stdint.h>

// Problem constants
#define BB 4
#define NN 2048
#define VD 256
#define CD 64
#define HH 4
#define DD 64
#define INNER 256
#define ROWS (BB * NN)   // 8192

typedef __nv_bfloat16 bf16;

// ---------------- scratch (device globals; no allocation allowed) ----------
__device__ float g_qkv[ROWS * 2 * INNER];
__device__ float g_qkc[ROWS * 2 * INNER];

__device__ bf16 g_Vnh[ROWS * VD];
__device__ bf16 g_Vnl[ROWS * VD];
__device__ bf16 g_Cnh[ROWS * CD];
__device__ bf16 g_Cnl[ROWS * CD];
__device__ bf16 g_ovph[ROWS * INNER];
__device__ bf16 g_ovpl[ROWS * INNER];
__device__ bf16 g_ocph[ROWS * INNER];
__device__ bf16 g_ocpl[ROWS * INNER];

__device__ bf16 g_Wvqk_h[VD * 512];
__device__ bf16 g_Wvqk_l[VD * 512];
__device__ bf16 g_Wcqk_h[CD * 512];
__device__ bf16 g_Wcqk_l[CD * 512];
__device__ bf16 g_Wvv_h[VD * INNER];
__device__ bf16 g_Wvv_l[VD * INNER];
__device__ bf16 g_Wcv_h[CD * INNER];
__device__ bf16 g_Wcv_l[CD * INNER];
__device__ bf16 g_Wov_h[INNER * VD];
__device__ bf16 g_Wov_l[INNER * VD];
__device__ bf16 g_Woc_h[INNER * CD];
__device__ bf16 g_Woc_l[INNER * CD];

// single fp16 Q/K/V, head-interleaved [row][h*128 + d]; Q has qscale folded in
__device__ __half g_Qf[ROWS * 512];
__device__ __half g_Kf[ROWS * 512];
__device__ __half g_Vf[ROWS * 512];

// ---------------- helpers ---------------------------------------------------
static __device__ __forceinline__ uint32_t smem_u32(const void* p) {
    return (uint32_t)__cvta_generic_to_shared(p);
}

static __device__ __forceinline__ void split1(float v, bf16& h, bf16& l) {
    float vh = __bfloat162float(__float2bfloat16_rn(v));
    h = __float2bfloat16_rn(vh);
    l = __float2bfloat16_rn(v - vh);
}

static __device__ __forceinline__ void split_pack2(float a, float b,
                                                   uint32_t& hi, uint32_t& lo) {
    float ah = __bfloat162float(__float2bfloat16_rn(a));
    float bh2 = __bfloat162float(__float2bfloat16_rn(b));
    __nv_bfloat162 h2 = __floats2bfloat162_rn(ah, bh2);
    __nv_bfloat162 l2 = __floats2bfloat162_rn(a - ah, b - bh2);
    hi = *(uint32_t*)&h2;
    lo = *(uint32_t*)&l2;
}

static __device__ __forceinline__ uint32_t pack_h2(float a, float b) {
    __half2 h = __floats2half2_rn(a, b);
    return *(uint32_t*)&h;
}

#define LDSM_X4(r0,r1,r2,r3,addr) \
    asm volatile("ldmatrix.sync.aligned.m8n8.x4.shared.b16 {%0,%1,%2,%3}, [%4];" \
        : "=r"(r0),"=r"(r1),"=r"(r2),"=r"(r3) : "r"(addr))

#define LDSM_X4_T(r0,r1,r2,r3,addr) \
    asm volatile("ldmatrix.sync.aligned.m8n8.x4.trans.shared.b16 {%0,%1,%2,%3}, [%4];" \
        : "=r"(r0),"=r"(r1),"=r"(r2),"=r"(r3) : "r"(addr))

#define MMA_BF16(C, A, b0_, b1_) \
    asm volatile("mma.sync.aligned.m16n8k16.row.col.f32.bf16.bf16.f32 " \
        "{%0,%1,%2,%3}, {%4,%5,%6,%7}, {%8,%9}, {%0,%1,%2,%3};" \
        : "+f"((C)[0]), "+f"((C)[1]), "+f"((C)[2]), "+f"((C)[3]) \
        : "r"((A)[0]), "r"((A)[1]), "r"((A)[2]), "r"((A)[3]), "r"(b0_), "r"(b1_))

#define MMA_F16(C, A, b0_, b1_) \
    asm volatile("mma.sync.aligned.m16n8k16.row.col.f32.f16.f16.f32 " \
        "{%0,%1,%2,%3}, {%4,%5,%6,%7}, {%8,%9}, {%0,%1,%2,%3};" \
        : "+f"((C)[0]), "+f"((C)[1]), "+f"((C)[2]), "+f"((C)[3]) \
        : "r"((A)[0]), "r"((A)[1]), "r"((A)[2]), "r"((A)[3]), "r"(b0_), "r"(b1_))

#define CP_A16(dst, src) \
    asm volatile("cp.async.cg.shared.global [%0], [%1], 16;" :: "r"(dst), "l"(src))
#define CP_COMMIT() asm volatile("cp.async.commit_group;")
#define CP_WAIT1() asm volatile("cp.async.wait_group 1;")
#define CP_WAIT0() asm volatile("cp.async.wait_group 0;")

// ---------------- LayerNorm + split-bf16 output ------------------------------
template <int DIM>
__global__ void ln_split_kernel(const float* __restrict__ x, const float* __restrict__ g,
                                const float* __restrict__ b,
                                bf16* __restrict__ oh, bf16* __restrict__ ol) {
    constexpr int NW = DIM / 32;
    __shared__ float red[NW];
    int row = blockIdx.x;
    int t = threadIdx.x;
    float v = x[(size_t)row * DIM + t];

    float s = v;
    #pragma unroll
    for (int o = 16; o; o >>= 1) s += __shfl_xor_sync(0xFFFFFFFFu, s, o);
    if ((t & 31) == 0) red[t >> 5] = s;
    __syncthreads();
    float tot = 0.f;
    #pragma unroll
    for (int i = 0; i < NW; i++) tot += red[i];
    float mean = tot / (float)DIM;
    __syncthreads();

    float d = v - mean;
    float s2 = d * d;
    #pragma unroll
    for (int o = 16; o; o >>= 1) s2 += __shfl_xor_sync(0xFFFFFFFFu, s2, o);
    if ((t & 31) == 0) red[t >> 5] = s2;
    __syncthreads();
    float var = 0.f;
    #pragma unroll
    for (int i = 0; i < NW; i++) var += red[i];
    var /= (float)DIM;

    float out = d * rsqrtf(var + 1e-5f) * g[t] + b[t];
    split1(out, oh[(size_t)row * DIM + t], ol[(size_t)row * DIM + t]);
}

// ---------------- merged weight split ----------------------------------------
__global__ void splitw_all_kernel(const float* __restrict__ Wvqk, const float* __restrict__ Wcqk,
                                  const float* __restrict__ Wvv,  const float* __restrict__ Wcv,
                                  const float* __restrict__ Wov,  const float* __restrict__ Woc) {
    int i = blockIdx.x * 256 + threadIdx.x;
    if (i < 131072) { split1(Wvqk[i], g_Wvqk_h[i], g_Wvqk_l[i]); return; }
    i -= 131072;
    if (i < 32768)  { split1(Wcqk[i], g_Wcqk_h[i], g_Wcqk_l[i]); return; }
    i -= 32768;
    if (i < 65536)  { split1(Wvv[i],  g_Wvv_h[i],  g_Wvv_l[i]);  return; }
    i -= 65536;
    if (i < 16384)  { split1(Wcv[i],  g_Wcv_h[i],  g_Wcv_l[i]);  return; }
    i -= 16384;
    if (i < 65536)  { split1(Wov[i],  g_Wov_h[i],  g_Wov_l[i]);  return; }
    i -= 65536;
    if (i < 16384)  { split1(Woc[i],  g_Woc_h[i],  g_Woc_l[i]); }
}

// ---- RMSNorm over 512 + fp16 write to head-interleaved Q/K buffers ---------
__global__ void rms512_f16_kernel(const float* __restrict__ x, const float* __restrict__ s,
                                  __half* __restrict__ Qf, __half* __restrict__ Kf,
                                  int coff) {
    __shared__ float red[8];
    int row = blockIdx.x;
    int t = threadIdx.x;
    const float* xr = x + (size_t)row * 512;
    float a = xr[t], c = xr[t + 256];
    float ss = a * a + c * c;
    #pragma unroll
    for (int o = 16; o; o >>= 1) ss += __shfl_xor_sync(0xFFFFFFFFu, ss, o);
    if ((t & 31) == 0) red[t >> 5] = ss;
    __syncthreads();
    float tot = 0.f;
    #pragma unroll
    for (int i = 0; i < 8; i++) tot += red[i];
    float r = rsqrtf(tot / 512.f + 1e-6f);

    float qv = a * r * s[t] * 0.125f;
    float kv = c * r * s[t + 256];
    int h = t >> 6, d = t & 63;
    size_t di = (size_t)row * 512 + h * 128 + coff + d;
    Qf[di] = __float2half_rn(qv);
    Kf[di] = __float2half_rn(kv);
}

// ---------------- Tensor-core GEMM (split-bf16 x3, pipelined) ----------------
struct GemmSmem {
    bf16 Ah[2][128][72];
    bf16 Al[2][128][72];
    bf16 Bh[2][64][72];
    bf16 Bl[2][64][72];
};  // 110,592 B

__global__ void __launch_bounds__(256)
mma_gemm_kernel(const bf16* __restrict__ Ah_, const bf16* __restrict__ Al_,
                const bf16* __restrict__ Bh_, const bf16* __restrict__ Bl_,
                const float* __restrict__ bias, float* __restrict__ C,
                int K, int Nc,
                bf16* __restrict__ oh, bf16* __restrict__ ol,
                __half* __restrict__ vf, int coff) {
    extern __shared__ char smraw[];
    GemmSmem& sm = *(GemmSmem*)smraw;
    int tid = threadIdx.x;
    int lane = tid & 31;
    int wid = tid >> 5;
    int m0 = wid * 16;
    int g = lane >> 2, t4 = lane & 3;
    int bm0 = blockIdx.y * 128;
    int bn0 = blockIdx.x * 64;

    const uint32_t AHL = 2 * 128 * 72 * 2;
    const uint32_t BHL = 2 * 64 * 72 * 2;
    float cC[8][4] = {};

    {
        for (int idx = tid; idx < 1024; idx += 256) {
            int tok = idx >> 3;
            int c8 = (idx & 7) << 3;
            size_t abase = (size_t)(bm0 + tok) * K + c8;
            CP_A16(smem_u32(&sm.Ah[0][tok][c8]), &Ah_[abase]);
            CP_A16(smem_u32(&sm.Al[0][tok][c8]), &Al_[abase]);
        }
        for (int idx = tid; idx < 512; idx += 256) {
            int tok = idx >> 3;
            int c8 = (idx & 7) << 3;
            size_t bbase = (size_t)tok * Nc + bn0 + c8;
            CP_A16(smem_u32(&sm.Bh[0][tok][c8]), &Bh_[bbase]);
            CP_A16(smem_u32(&sm.Bl[0][tok][c8]), &Bl_[bbase]);
        }
        CP_COMMIT();
    }

    int NKS = K >> 6;
    for (int ks = 0; ks < NKS; ks++) {
        int st = ks & 1;
        if (ks + 1 < NKS) {
            int st1 = (ks + 1) & 1;
            int k1 = (ks + 1) * 64;
            for (int idx = tid; idx < 1024; idx += 256) {
                int tok = idx >> 3;
                int c8 = (idx & 7) << 3;
                size_t abase = (size_t)(bm0 + tok) * K + k1 + c8;
                CP_A16(smem_u32(&sm.Ah[st1][tok][c8]), &Ah_[abase]);
                CP_A16(smem_u32(&sm.Al[st1][tok][c8]), &Al_[abase]);
            }
            for (int idx = tid; idx < 512; idx += 256) {
                int tok = idx >> 3;
                int c8 = (idx & 7) << 3;
                size_t bbase = (size_t)(k1 + tok) * Nc + bn0 + c8;
                CP_A16(smem_u32(&sm.Bh[st1][tok][c8]), &Bh_[bbase]);
                CP_A16(smem_u32(&sm.Bl[st1][tok][c8]), &Bl_[bbase]);
            }
            CP_COMMIT();
            CP_WAIT1();
        } else {
            CP_WAIT0();
        }
        __syncthreads();

        #pragma unroll
        for (int j = 0; j < 4; j++) {
            uint32_t ah[4], al[4];
            uint32_t aaddr = smem_u32(&sm.Ah[st][m0 + (lane & 15)][j * 16 + (lane >> 4) * 8]);
            LDSM_X4(ah[0], ah[1], ah[2], ah[3], aaddr);
            LDSM_X4(al[0], al[1], al[2], al[3], aaddr + AHL);
            #pragma unroll
            for (int p = 0; p < 2; p++) {
                uint32_t bh2[2][4], bl2[2][4];
                #pragma unroll
                for (int q = 0; q < 2; q++) {
                    int nh = 2 * p + q;
                    uint32_t baddr = smem_u32(&sm.Bh[st][j * 16 + ((lane >> 3) & 1) * 8 + (lane & 7)]
                                                    [nh * 16 + (lane >> 4) * 8]);
                    LDSM_X4_T(bh2[q][0], bh2[q][1], bh2[q][2], bh2[q][3], baddr);
                    LDSM_X4_T(bl2[q][0], bl2[q][1], bl2[q][2], bl2[q][3], baddr + BHL);
                }
                float* c0 = cC[4 * p + 0]; float* c1 = cC[4 * p + 1];
                float* c2 = cC[4 * p + 2]; float* c3 = cC[4 * p + 3];
                MMA_BF16(c0, ah, bh2[0][0], bh2[0][1]);
                MMA_BF16(c1, ah, bh2[0][2], bh2[0][3]);
                MMA_BF16(c2, ah, bh2[1][0], bh2[1][1]);
                MMA_BF16(c3, ah, bh2[1][2], bh2[1][3]);
                MMA_BF16(c0, ah, bl2[0][0], bl2[0][1]);
                MMA_BF16(c1, ah, bl2[0][2], bl2[0][3]);
                MMA_BF16(c2, ah, bl2[1][0], bl2[1][1]);
                MMA_BF16(c3, ah, bl2[1][2], bl2[1][3]);
                MMA_BF16(c0, al, bh2[0][0], bh2[0][1]);
                MMA_BF16(c1, al, bh2[0][2], bh2[0][3]);
                MMA_BF16(c2, al, bh2[1][0], bh2[1][1]);
                MMA_BF16(c3, al, bh2[1][2], bh2[1][3]);
            }
        }
        __syncthreads();
    }

    int r0 = bm0 + m0 + g;
    if (oh) {
        #pragma unroll
        for (int nf = 0; nf < 8; nf++) {
            int n = bn0 + nf * 8 + t4 * 2;
            float b0 = bias[n], b1 = bias[n + 1];
            size_t di0 = (size_t)r0 * 512 + ((n >> 6) * 128 + coff + (n & 63));
            size_t di1 = (size_t)(r0 + 8) * 512 + ((n >> 6) * 128 + coff + (n & 63));
            uint32_t h0, l0, h1, l1;
            split_pack2(cC[nf][0] + b0, cC[nf][1] + b1, h0, l0);
            split_pack2(cC[nf][2] + b0, cC[nf][3] + b1, h1, l1);
            *(uint32_t*)&oh[di0] = h0; *(uint32_t*)&ol[di0] = l0;
            *(uint32_t*)&oh[di1] = h1; *(uint32_t*)&ol[di1] = l1;
        }
    } else if (vf) {
        // fp16 single-value head-interleaved epilogue (V buffer)
        #pragma unroll
        for (int nf = 0; nf < 8; nf++) {
            int n = bn0 + nf * 8 + t4 * 2;
            float b0 = bias[n], b1 = bias[n + 1];
            size_t di0 = (size_t)r0 * 512 + ((n >> 6) * 128 + coff + (n & 63));
            size_t di1 = (size_t)(r0 + 8) * 512 + ((n >> 6) * 128 + coff + (n & 63));
            *(uint32_t*)&vf[di0] = pack_h2(cC[nf][0] + b0, cC[nf][1] + b1);
            *(uint32_t*)&vf[di1] = pack_h2(cC[nf][2] + b0, cC[nf][3] + b1);
        }
    } else {
        #pragma unroll
        for (int nf = 0; nf < 8; nf++) {
            int n = bn0 + nf * 8 + t4 * 2;
            float b0 = bias[n], b1 = bias[n + 1];
            *(float2*)&C[(size_t)r0 * Nc + n] =
                make_float2(cC[nf][0] + b0, cC[nf][1] + b1);
            *(float2*)&C[(size_t)(r0 + 8) * Nc + n] =
                make_float2(cC[nf][2] + b0, cC[nf][3] + b1);
        }
    }
}

// ---------------- Tensor-core attention (all-fp16 operands) ------------------
// TQ=128, 8 warps x 16 rows. QK single fp16, PV single fp16; fp32 accum +
// fp32 register softmax. 2-stage cp.async for K/V. 104.4 KB smem -> occ 2.
struct AttnSmem {
    __half Qf[128][136];      // 34,816 B
    __half Kf[2][64][136];    // 34,816 B
    __half Vf[2][64][136];    // 34,816 B
};  // 104,448 B

__global__ void __launch_bounds__(256, 2)
attn_kernel(const __half* __restrict__ gQf, const __half* __restrict__ gKf,
            const __half* __restrict__ gVf,
            bf16* __restrict__ ovph, bf16* __restrict__ ovpl,
            bf16* __restrict__ ocph, bf16* __restrict__ ocpl) {
    extern __shared__ char smraw[];
    AttnSmem& sm = *(AttnSmem*)smraw;
    int tid = threadIdx.x;
    int lane = tid & 31;
    int wid = tid >> 5;       // 0..7
    int m0 = wid * 16;
    int g = lane >> 2, t4 = lane & 3;

    int bh_ = blockIdx.y;
    int b = bh_ >> 2;
    int h = bh_ & 3;
    int n0q = blockIdx.x * 128;

    const uint32_t KHL = 0;   // (unused)

    // ---- Fill Q tile (fp16) ----
    for (int idx = tid; idx < 2048; idx += 256) {
        int tok = idx >> 4;
        int c8 = (idx & 15) << 3;
        size_t base = (size_t)(b * NN + n0q + tok) * 512 + h * 128 + c8;
        *(uint4*)&sm.Qf[tok][c8] = *(const uint4*)&gQf[base];
    }

    float m_[2] = {-1e30f, -1e30f};
    float l_[2] = {0.f, 0.f};
    float cO[16][4] = {};

    // ---- prologue: prefetch tile 0 into stage 0 ----
    {
        for (int idx = tid; idx < 1024; idx += 256) {
            int tok = idx >> 4;
            int c8 = (idx & 15) << 3;
            size_t base = (size_t)(b * NN + tok) * 512 + h * 128 + c8;
            CP_A16(smem_u32(&sm.Kf[0][tok][c8]), &gKf[base]);
            CP_A16(smem_u32(&sm.Vf[0][tok][c8]), &gVf[base]);
        }
        CP_COMMIT();
    }

    const int NT = NN / 64;
    for (int jt = 0; jt < NT; jt++) {
        int st = jt & 1;
        if (jt + 1 < NT) {
            int kn1 = (jt + 1) * 64;
            int st1 = (jt + 1) & 1;
            for (int idx = tid; idx < 1024; idx += 256) {
                int tok = idx >> 4;
                int c8 = (idx & 15) << 3;
                size_t base = (size_t)(b * NN + kn1 + tok) * 512 + h * 128 + c8;
                CP_A16(smem_u32(&sm.Kf[st1][tok][c8]), &gKf[base]);
                CP_A16(smem_u32(&sm.Vf[st1][tok][c8]), &gVf[base]);
            }
            CP_COMMIT();
            CP_WAIT1();
        } else {
            CP_WAIT0();
        }
        __syncthreads();

        // ---- S = Q @ K^T : single fp16 MMA ----
        float cS[8][4] = {};
        #pragma unroll
        for (int kf = 0; kf < 8; kf++) {
            int k0 = kf * 16;
            uint32_t ah[4];
            uint32_t aaddr = smem_u32(&sm.Qf[m0 + (lane & 15)][k0 + (lane >> 4) * 8]);
            LDSM_X4(ah[0], ah[1], ah[2], ah[3], aaddr);
            #pragma unroll
            for (int p = 0; p < 2; p++) {
                uint32_t bh2[2][4];
                #pragma unroll
                for (int q = 0; q < 2; q++) {
                    int nb = 2 * p + q;
                    uint32_t baddr = smem_u32(&sm.Kf[st][nb * 16 + ((lane >> 4) & 1) * 8 + (lane & 7)]
                                                    [k0 + ((lane >> 3) & 1) * 8]);
                    LDSM_X4(bh2[q][0], bh2[q][1], bh2[q][2], bh2[q][3], baddr);
                }
                MMA_F16(cS[4 * p + 0], ah, bh2[0][0], bh2[0][1]);
                MMA_F16(cS[4 * p + 1], ah, bh2[0][2], bh2[0][3]);
                MMA_F16(cS[4 * p + 2], ah, bh2[1][0], bh2[1][1]);
                MMA_F16(cS[4 * p + 3], ah, bh2[1][2], bh2[1][3]);
            }
        }

        // ---- Register online softmax ----
        #pragma unroll
        for (int r = 0; r < 2; r++) {
            float mx = -1e30f;
            #pragma unroll
            for (int n = 0; n < 8; n++)
                mx = fmaxf(mx, fmaxf(cS[n][2 * r], cS[n][2 * r + 1]));
            mx = fmaxf(mx, __shfl_xor_sync(0xFFFFFFFFu, mx, 1));
            mx = fmaxf(mx, __shfl_xor_sync(0xFFFFFFFFu, mx, 2));
            float m_new = fmaxf(m_[r], mx);
            float alpha = __expf(m_[r] - m_new);
            float sum = 0.f;
            #pragma unroll
            for (int n = 0; n < 8; n++) {
                float p0 = __expf(cS[n][2 * r]     - m_new);
                float p1 = __expf(cS[n][2 * r + 1] - m_new);
                cS[n][2 * r] = p0; cS[n][2 * r + 1] = p1;
                sum += p0 + p1;
            }
            sum += __shfl_xor_sync(0xFFFFFFFFu, sum, 1);
            sum += __shfl_xor_sync(0xFFFFFFFFu, sum, 2);
            l_[r] = l_[r] * alpha + sum;
            m_[r] = m_new;
            #pragma unroll
            for (int nf = 0; nf < 16; nf++) {
                cO[nf][2 * r]     *= alpha;
                cO[nf][2 * r + 1] *= alpha;
            }
        }

        // ---- O += P @ V : single fp16 MMA ----
        #pragma unroll
        for (int j = 0; j < 4; j++) {
            uint32_t PhA[4];
            PhA[0] = pack_h2(cS[2 * j][0],     cS[2 * j][1]);
            PhA[1] = pack_h2(cS[2 * j][2],     cS[2 * j][3]);
            PhA[2] = pack_h2(cS[2 * j + 1][0], cS[2 * j + 1][1]);
            PhA[3] = pack_h2(cS[2 * j + 1][2], cS[2 * j + 1][3]);
            #pragma unroll
            for (int p = 0; p < 4; p++) {
                uint32_t bh2[2][4];
                #pragma unroll
                for (int q = 0; q < 2; q++) {
                    int nh = 2 * p + q;
                    uint32_t baddr = smem_u32(&sm.Vf[st][j * 16 + ((lane >> 3) & 1) * 8 + (lane & 7)]
                                                    [nh * 16 + (lane >> 4) * 8]);
                    LDSM_X4_T(bh2[q][0], bh2[q][1], bh2[q][2], bh2[q][3], baddr);
                }
                MMA_F16(cO[4 * p + 0], PhA, bh2[0][0], bh2[0][1]);
                MMA_F16(cO[4 * p + 1], PhA, bh2[0][2], bh2[0][3]);
                MMA_F16(cO[4 * p + 2], PhA, bh2[1][0], bh2[1][1]);
                MMA_F16(cO[4 * p + 3], PhA, bh2[1][2], bh2[1][3]);
            }
        }
        __syncthreads();   // stage st free for prefetch of jt+2
    }

    // ---- Epilogue: normalize, split-bf16 write ----
    float li0 = 1.f / l_[0];
    float li1 = 1.f / l_[1];
    size_t row0 = (size_t)(b * NN + n0q + m0 + g);
    size_t row1 = row0 + 8;
    #pragma unroll
    for (int nf = 0; nf < 16; nf++) {
        int c = nf * 8 + t4 * 2;
        uint32_t h0, l0, h1, l1;
        split_pack2(cO[nf][0] * li0, cO[nf][1] * li0, h0, l0);
        split_pack2(cO[nf][2] * li1, cO[nf][3] * li1, h1, l1);
        if (c < 64) {
            size_t d0 = row0 * 256 + h * 64 + c, d1 = row1 * 256 + h * 64 + c;
            *(uint32_t*)&ovph[d0] = h0; *(uint32_t*)&ovpl[d0] = l0;
            *(uint32_t*)&ovph[d1] = h1; *(uint32_t*)&ovpl[d1] = l1;
        } else {
            size_t d0 = row0 * 256 + h * 64 + (c - 64), d1 = row1 * 256 + h * 64 + (c - 64);
            *(uint32_t*)&ocph[d0] = h0; *(uint32_t*)&ocpl[d0] = l0;
            *(uint32_t*)&ocph[d1] = h1; *(uint32_t*)&ocpl[d1] = l1;
        }
    }
}

// ---------------- launch ----------------------------------------------------
extern "C" void kernel_launch(void* const* d_in, const int* in_sizes, int n_in,
                              void* d_out, int out_size) {
    const float* V     = (const float*)d_in[0];
    const float* C     = (const float*)d_in[1];
    const float* vn_g  = (const float*)d_in[2];
    const float* vn_b  = (const float*)d_in[3];
    const float* cn_g  = (const float*)d_in[4];
    const float* cn_b  = (const float*)d_in[5];
    const float* W_vqk = (const float*)d_in[6];
    const float* b_vqk = (const float*)d_in[7];
    const float* rms_v = (const float*)d_in[8];
    const float* W_cqk = (const float*)d_in[9];
    const float* b_cqk = (const float*)d_in[10];
    const float* rms_c = (const float*)d_in[11];
    const float* W_vv  = (const float*)d_in[12];
    const float* b_vv  = (const float*)d_in[13];
    const float* W_cv  = (const float*)d_in[14];
    const float* b_cv  = (const float*)d_in[15];
    const float* W_ov  = (const float*)d_in[16];
    const float* b_ov  = (const float*)d_in[17];
    const float* W_oc  = (const float*)d_in[18];
    const float* b_oc  = (const float*)d_in[19];

    float* out_v = (float*)d_out;
    float* out_c = out_v + (size_t)ROWS * VD;

    float *pqkv, *pqkc;
    bf16 *pVnh, *pVnl, *pCnh, *pCnl;
    __half *pQf, *pKf, *pVf;
    bf16 *povph, *povpl, *pocph, *pocpl;
    bf16 *wvqkh, *wvqkl, *wcqkh, *wcqkl, *wvvh, *wvvl, *wcvh, *wcvl, *wovh, *wovl, *woch, *wocl;
    cudaGetSymbolAddress((void**)&pqkv, g_qkv);
    cudaGetSymbolAddress((void**)&pqkc, g_qkc);
    cudaGetSymbolAddress((void**)&pVnh, g_Vnh);
    cudaGetSymbolAddress((void**)&pVnl, g_Vnl);
    cudaGetSymbolAddress((void**)&pCnh, g_Cnh);
    cudaGetSymbolAddress((void**)&pCnl, g_Cnl);
    cudaGetSymbolAddress((void**)&pQf, g_Qf);
    cudaGetSymbolAddress((void**)&pKf, g_Kf);
    cudaGetSymbolAddress((void**)&pVf, g_Vf);
    cudaGetSymbolAddress((void**)&povph, g_ovph);
    cudaGetSymbolAddress((void**)&povpl, g_ovpl);
    cudaGetSymbolAddress((void**)&pocph, g_ocph);
    cudaGetSymbolAddress((void**)&pocpl, g_ocpl);
    cudaGetSymbolAddress((void**)&wvqkh, g_Wvqk_h);
    cudaGetSymbolAddress((void**)&wvqkl, g_Wvqk_l);
    cudaGetSymbolAddress((void**)&wcqkh, g_Wcqk_h);
    cudaGetSymbolAddress((void**)&wcqkl, g_Wcqk_l);
    cudaGetSymbolAddress((void**)&wvvh, g_Wvv_h);
    cudaGetSymbolAddress((void**)&wvvl, g_Wvv_l);
    cudaGetSymbolAddress((void**)&wcvh, g_Wcv_h);
    cudaGetSymbolAddress((void**)&wcvl, g_Wcv_l);
    cudaGetSymbolAddress((void**)&wovh, g_Wov_h);
    cudaGetSymbolAddress((void**)&wovl, g_Wov_l);
    cudaGetSymbolAddress((void**)&woch, g_Woc_h);
    cudaGetSymbolAddress((void**)&wocl, g_Woc_l);

    // 1. LayerNorms + merged weight split
    ln_split_kernel<VD><<<ROWS, VD>>>(V, vn_g, vn_b, pVnh, pVnl);
    ln_split_kernel<CD><<<ROWS, CD>>>(C, cn_g, cn_b, pCnh, pCnl);
    splitw_all_kernel<<<(327680 + 255) / 256, 256>>>(W_vqk, W_cqk, W_vv, W_cv, W_ov, W_oc);

    // 2. Projections
    cudaFuncSetAttribute(mma_gemm_kernel, cudaFuncAttributeMaxDynamicSharedMemorySize,
                         (int)sizeof(GemmSmem));
    int gsm = (int)sizeof(GemmSmem);
    mma_gemm_kernel<<<dim3(512 / 64, ROWS / 128), 256, gsm>>>(pVnh, pVnl, wvqkh, wvqkl, b_vqk, pqkv,
                                                              VD, 512, nullptr, nullptr, nullptr, 0);
    mma_gemm_kernel<<<dim3(512 / 64, ROWS / 128), 256, gsm>>>(pCnh, pCnl, wcqkh, wcqkl, b_cqk, pqkc,
                                                              CD, 512, nullptr, nullptr, nullptr, 0);
    mma_gemm_kernel<<<dim3(256 / 64, ROWS / 128), 256, gsm>>>(pVnh, pVnl, wvvh, wvvl, b_vv, nullptr,
                                                              VD, 256, nullptr, nullptr, pVf, 0);
    mma_gemm_kernel<<<dim3(256 / 64, ROWS / 128), 256, gsm>>>(pCnh, pCnl, wcvh, wcvl, b_cv, nullptr,
                                                              CD, 256, nullptr, nullptr, pVf, 64);

    // 3. RMS norms + fp16 Q/K writes
    rms512_f16_kernel<<<ROWS, 256>>>(pqkv, rms_v, pQf, pKf, 0);
    rms512_f16_kernel<<<ROWS, 256>>>(pqkc, rms_c, pQf, pKf, 64);

    // 4. Attention (all-fp16 operands, occ 2)
    cudaFuncSetAttribute(attn_kernel, cudaFuncAttributeMaxDynamicSharedMemorySize,
                         (int)sizeof(AttnSmem));
    attn_kernel<<<dim3(NN / 128, BB * HH), 256, sizeof(AttnSmem)>>>(pQf, pKf, pVf,
                                                                    povph, povpl, pocph, pocpl);

    // 5. Output projections
    mma_gemm_kernel<<<dim3(256 / 64, ROWS / 128), 256, gsm>>>(povph, povpl, wovh, wovl, b_ov, out_v,
                                                              INNER, VD, nullptr, nullptr, nullptr, 0);
    mma_gemm_kernel<<<dim3(64 / 64, ROWS / 128), 256, gsm>>>(pocph, pocpl, woch, wocl, b_oc, out_c,
                                                             INNER, CD, nullptr, nullptr, nullptr, 0);
}